// round 1
// baseline (speedup 1.0000x reference)
#include <cuda_runtime.h>
#include <cstdint>

// Problem constants (256x256 grid, 4-adjacency)
#define L_     65536      // leaves
#define NN     131071     // 2L-1 nodes
#define NPAD   262144     // 2^18, >= 130560 edges, power of two for bitonic

// ---------------- device scratch (no allocations allowed) ----------------
__device__ unsigned long long g_keys[NPAD];   // (weight_bits<<32)|edge_idx, sorted ascending
__device__ unsigned int       g_uf[NN];       // union-find over node ids
__device__ unsigned int       g_parent[NN];   // BPT parent (root -> self)
__device__ float              g_sizes[NN];    // subtree leaf counts
__device__ float              g_alt[NN];      // altitude (0 for leaves, edge weight for internals)

// ---------------- init ----------------
__global__ void k_init(const float* __restrict__ ew, int M) {
    int i = blockIdx.x * blockDim.x + threadIdx.x;
    if (i < NPAD) {
        if (i < M) {
            unsigned int wb = __float_as_uint(ew[i]);  // weights in [0,1): bits monotone
            g_keys[i] = ((unsigned long long)wb << 32) | (unsigned int)i;
        } else {
            g_keys[i] = ~0ull;  // padding sorts to the end
        }
    }
    if (i < NN) {
        g_uf[i]     = i;
        g_parent[i] = i;
        g_sizes[i]  = (i < L_) ? 1.0f : 0.0f;
        g_alt[i]    = 0.0f;
    }
}

// ---------------- bitonic sort (unique 64-bit keys => stability for free) ----------------
// Local kernel: all phases k=2..2048 inside one block of 2048 elements.
__global__ void k_bitonic_local_init() {
    __shared__ unsigned long long s[2048];
    int base = blockIdx.x * 2048;
    int t = threadIdx.x;  // 1024 threads
    s[t]        = g_keys[base + t];
    s[t + 1024] = g_keys[base + t + 1024];
    __syncthreads();
    for (int k = 2; k <= 2048; k <<= 1) {
        for (int j = k >> 1; j > 0; j >>= 1) {
            int pos = ((t & ~(j - 1)) << 1) | (t & (j - 1));
            int gi  = base + pos;
            bool asc = ((gi & k) == 0);
            unsigned long long x = s[pos], y = s[pos + j];
            if ((x > y) == asc) { s[pos] = y; s[pos + j] = x; }
            __syncthreads();
        }
    }
    g_keys[base + t]        = s[t];
    g_keys[base + t + 1024] = s[t + 1024];
}

// One global compare-exchange step (j >= 2048).
__global__ void k_bitonic_global(int j, int k) {
    int t = blockIdx.x * blockDim.x + threadIdx.x;  // NPAD/2 threads
    int i = ((t & ~(j - 1)) << 1) | (t & (j - 1));
    int l = i + j;
    bool asc = ((i & k) == 0);
    unsigned long long x = g_keys[i], y = g_keys[l];
    if ((x > y) == asc) { g_keys[i] = y; g_keys[l] = x; }
}

// Local tail: for a given k (>= 4096), handle j = 1024..1 in shared memory.
__global__ void k_bitonic_local_tail(int k) {
    __shared__ unsigned long long s[2048];
    int base = blockIdx.x * 2048;
    int t = threadIdx.x;
    s[t]        = g_keys[base + t];
    s[t + 1024] = g_keys[base + t + 1024];
    __syncthreads();
    bool asc = ((base & k) == 0);  // k >= 4096 > 2048: constant per block
    for (int j = 1024; j > 0; j >>= 1) {
        int pos = ((t & ~(j - 1)) << 1) | (t & (j - 1));
        unsigned long long x = s[pos], y = s[pos + j];
        if ((x > y) == asc) { s[pos] = y; s[pos + j] = x; }
        __syncthreads();
    }
    g_keys[base + t]        = s[t];
    g_keys[base + t + 1024] = s[t + 1024];
}

// ---------------- Kruskal / BPT build (single warp, speculative finds) ----------------
__device__ __forceinline__ unsigned int uf_find(unsigned int x) {
    for (;;) {
        unsigned int p = g_uf[x];
        if (p == x) return x;
        unsigned int gp = g_uf[p];
        if (gp == p) return p;
        g_uf[x] = gp;   // path halving (racy but invariant-preserving: always an ancestor)
        x = gp;
    }
}

__global__ void k_kruskal(const int* __restrict__ src, const int* __restrict__ dst, int M) {
    int lane = threadIdx.x;
    __shared__ unsigned int s_node;
    if (lane == 0) s_node = L_;
    __syncwarp();

    for (int base = 0; base < M; base += 32) {
        int e = base + lane;
        bool act = (e < M);
        unsigned int a = 0, b = 0;
        unsigned long long key = 0;
        if (act) {
            key = g_keys[e];
            unsigned int idx = (unsigned int)key;   // original edge index
            // speculative parallel finds: 32-way MLP hides latency
            a = uf_find((unsigned int)src[idx]);
            b = uf_find((unsigned int)dst[idx]);
        }
        // serial in-order commit
        for (int j = 0; j < 32; j++) {
            if (lane == j && act) {
                a = uf_find(a);   // cheap re-walk from speculative roots
                b = uf_find(b);
                if (a != b) {
                    unsigned int node = atomicAdd(&s_node, 1u);
                    g_uf[a] = node;     g_uf[b] = node;
                    g_parent[a] = node; g_parent[b] = node;
                    g_sizes[node] = g_sizes[a] + g_sizes[b];
                    g_alt[node]   = __uint_as_float((unsigned int)(key >> 32));
                }
            }
            __syncwarp();  // fences memory among warp lanes
        }
    }
}

// ---------------- softarea ----------------
__global__ void k_zero(float* __restrict__ out) {
    int i = blockIdx.x * blockDim.x + threadIdx.x;
    if (i < NN) out[i] = 0.0f;
}

__device__ __forceinline__ float sigm(float x) {
    return 1.0f / (1.0f + __expf(-x));   // LAM = 1
}

__global__ void k_softarea(float* __restrict__ out) {
    int n = blockIdx.x * blockDim.x + threadIdx.x;
    if (n >= NN) return;

    // outside(n) = sum over ancestor steps (c -> p): (size[p]-size[c]) * sigmoid(alt[n]-alt[p])
    float altn = g_alt[n];
    float outside = 0.0f;
    unsigned int c = (unsigned int)n;
    float szc = g_sizes[c];
    for (;;) {
        unsigned int p = g_parent[c];
        if (p == c) break;
        float szp = g_sizes[p];
        outside += (szp - szc) * sigm(altn - g_alt[p]);
        c = p; szc = szp;
    }

    float self = outside;
    if (n < L_) {
        self += 0.5f;  // inside.at[:L].add(0.5)
        // inside contributions: for each strict ancestor a of leaf n (root counted once):
        //   inside[a] += sigmoid(alt[a] - alt[parent(n)])
        unsigned int a = g_parent[n];
        float alt1 = g_alt[a];
        for (;;) {
            atomicAdd(&out[a], sigm(g_alt[a] - alt1));
            unsigned int pa = g_parent[a];
            if (pa == a) break;
            a = pa;
        }
    }
    atomicAdd(&out[n], self);
}

// ---------------- launch ----------------
extern "C" void kernel_launch(void* const* d_in, const int* in_sizes, int n_in,
                              void* d_out, int out_size) {
    const float* ew  = (const float*)d_in[0];
    const int*   src = (const int*)d_in[1];
    const int*   dst = (const int*)d_in[2];
    int M = in_sizes[0];   // 130560

    k_init<<<NPAD / 256, 256>>>(ew, M);

    // bitonic sort of g_keys[0..NPAD)
    k_bitonic_local_init<<<NPAD / 2048, 1024>>>();
    for (int k = 4096; k <= NPAD; k <<= 1) {
        for (int j = k >> 1; j >= 2048; j >>= 1)
            k_bitonic_global<<<(NPAD / 2) / 256, 256>>>(j, k);
        k_bitonic_local_tail<<<NPAD / 2048, 1024>>>(k);
    }

    k_kruskal<<<1, 32>>>(src, dst, M);

    float* out = (float*)d_out;
    k_zero<<<(NN + 255) / 256, 256>>>(out);
    k_softarea<<<(NN + 255) / 256, 256>>>(out);
}

// round 2
// speedup vs baseline: 1.1300x; 1.1300x over previous
#include <cuda_runtime.h>
#include <cstdint>

// Problem constants (256x256 grid, 4-adjacency)
#define L_    65536      // leaves
#define NN    131071     // 2L-1 nodes
#define NPAD  262144     // 2^18 >= 130560 edges
#define MMAX  130560
#define BT    1024       // build-kernel threads
#define EPT   4          // edges per thread per round
#define BRND  (BT*EPT)   // 4096 edges per round

// ---------------- device scratch ----------------
__device__ unsigned long long g_keys[NPAD];  // (wbits<<32)|edge_idx, sorted asc
__device__ unsigned int g_ufv[L_];           // union-find over vertices (union by min)
__device__ unsigned int g_mark[L_];          // version-stamped min-edge marks
__device__ unsigned int g_rec[MMAX];         // accepted rank k -> (win<<16)|lose
__device__ unsigned int g_nid[MMAX];         // accepted rank k -> node id (L_+i); ~0 = rejected
__device__ unsigned int g_parent[NN];
__device__ float        g_alt[NN];
__device__ float        g_sizes[NN];
__device__ unsigned int g_cnt[L_];           // per-vertex event counts / cursors
__device__ unsigned int g_offs[L_];
__device__ unsigned int g_evt[2 * (L_ - 1)]; // event ranks, grouped by vertex

// ---------------- init ----------------
__global__ void k_init(const float* __restrict__ ew, int M) {
    int i = blockIdx.x * blockDim.x + threadIdx.x;
    if (i < NPAD) {
        if (i < M) {
            unsigned int wb = __float_as_uint(ew[i]);  // weights in [0,1): bits monotone
            g_keys[i] = ((unsigned long long)wb << 32) | (unsigned int)i;
        } else {
            g_keys[i] = ~0ull;
        }
    }
    if (i < L_) { g_ufv[i] = i; g_mark[i] = 0xFFFFFFFFu; g_cnt[i] = 0u; }
    if (i < NN) { g_parent[i] = i; g_alt[i] = 0.0f; g_sizes[i] = (i < L_) ? 1.0f : 0.0f; }
    if (i < MMAX) g_nid[i] = 0xFFFFFFFFu;
}

// ---------------- bitonic sort (unique 64-bit keys => stability for free) ----------------
__global__ void k_bitonic_local_init() {
    __shared__ unsigned long long s[2048];
    int base = blockIdx.x * 2048;
    int t = threadIdx.x;
    s[t]        = g_keys[base + t];
    s[t + 1024] = g_keys[base + t + 1024];
    __syncthreads();
    for (int k = 2; k <= 2048; k <<= 1) {
        for (int j = k >> 1; j > 0; j >>= 1) {
            int pos = ((t & ~(j - 1)) << 1) | (t & (j - 1));
            int gi  = base + pos;
            bool asc = ((gi & k) == 0);
            unsigned long long x = s[pos], y = s[pos + j];
            if ((x > y) == asc) { s[pos] = y; s[pos + j] = x; }
            __syncthreads();
        }
    }
    g_keys[base + t]        = s[t];
    g_keys[base + t + 1024] = s[t + 1024];
}

__global__ void k_bitonic_global(int j, int k) {
    int t = blockIdx.x * blockDim.x + threadIdx.x;
    int i = ((t & ~(j - 1)) << 1) | (t & (j - 1));
    int l = i + j;
    bool asc = ((i & k) == 0);
    unsigned long long x = g_keys[i], y = g_keys[l];
    if ((x > y) == asc) { g_keys[i] = y; g_keys[l] = x; }
}

__global__ void k_bitonic_local_tail(int k) {
    __shared__ unsigned long long s[2048];
    int base = blockIdx.x * 2048;
    int t = threadIdx.x;
    s[t]        = g_keys[base + t];
    s[t + 1024] = g_keys[base + t + 1024];
    __syncthreads();
    bool asc = ((base & k) == 0);
    for (int j = 1024; j > 0; j >>= 1) {
        int pos = ((t & ~(j - 1)) << 1) | (t & (j - 1));
        unsigned long long x = s[pos], y = s[pos + j];
        if ((x > y) == asc) { s[pos] = y; s[pos + j] = x; }
        __syncthreads();
    }
    g_keys[base + t]        = s[t];
    g_keys[base + t + 1024] = s[t + 1024];
}

// ---------------- union-find (path halving; benign races) ----------------
__device__ __forceinline__ unsigned int uf_find(unsigned int x) {
    for (;;) {
        unsigned int p = g_ufv[x];
        if (p == x) return x;
        unsigned int gp = g_ufv[p];
        if (gp == p) return p;
        g_ufv[x] = gp;
        x = gp;
    }
}

// ---------------- batched-parallel Kruskal (single block) ----------------
__global__ void k_build(const int* __restrict__ src, const int* __restrict__ dst, int M) {
    __shared__ unsigned int s_scan[BT];
    __shared__ unsigned int s_flag, s_iter, s_base;
    int t = threadIdx.x;
    if (t == 0) { s_iter = 0u; s_base = 0u; }
    __syncthreads();

    int nrounds = (M + BRND - 1) / BRND;
    for (int r = 0; r < nrounds; r++) {
        int lo = r * BRND;
        unsigned int eu[EPT], ev[EPT], wb[EPT], av[EPT], bv[EPT];
        int st[EPT];   // 0=active 1=done(rejected/pad) 2=accepted
        #pragma unroll
        for (int i = 0; i < EPT; i++) {
            int e = lo + t * EPT + i;
            if (e < M) {
                unsigned long long key = g_keys[e];
                unsigned int idx = (unsigned int)key;
                eu[i] = (unsigned int)src[idx];
                ev[i] = (unsigned int)dst[idx];
                wb[i] = (unsigned int)(key >> 32);
                st[i] = 0;
            } else st[i] = 1;
        }

        for (;;) {
            __syncthreads();
            if (t == 0) { s_flag = 0u; s_iter++; }
            __syncthreads();
            unsigned int iter = s_iter;

            // mark phase
            #pragma unroll
            for (int i = 0; i < EPT; i++) {
                if (st[i] == 0) {
                    unsigned int a = uf_find(eu[i]);
                    unsigned int b = uf_find(ev[i]);
                    if (a == b) { st[i] = 1; continue; }   // rejected forever
                    av[i] = a; bv[i] = b;
                    unsigned int pk = ((0xFFFFu - iter) << 16) | (unsigned int)(t * EPT + i);
                    atomicMin(&g_mark[a], pk);
                    atomicMin(&g_mark[b], pk);
                }
            }
            __syncthreads();

            // commit phase: commit iff min-holder on BOTH roots (disjoint => parallel-safe)
            bool rem = false;
            #pragma unroll
            for (int i = 0; i < EPT; i++) {
                if (st[i] == 0) {
                    unsigned int pk = ((0xFFFFu - iter) << 16) | (unsigned int)(t * EPT + i);
                    if (g_mark[av[i]] == pk && g_mark[bv[i]] == pk) {
                        unsigned int a = av[i], b = bv[i];
                        unsigned int w = a < b ? a : b;
                        unsigned int l = a < b ? b : a;
                        g_ufv[l] = w;                                // union by min vertex
                        g_rec[lo + t * EPT + i] = (w << 16) | l;     // merge record
                        st[i] = 2;
                    } else rem = true;
                }
            }
            if (rem) s_flag = 1u;
            __syncthreads();
            if (s_flag == 0u) break;
        }

        // round-end: assign node ids in rank order (block exclusive scan)
        unsigned int c = 0;
        #pragma unroll
        for (int i = 0; i < EPT; i++) if (st[i] == 2) c++;
        s_scan[t] = c;
        __syncthreads();
        for (int off = 1; off < BT; off <<= 1) {
            unsigned int x = (t >= off) ? s_scan[t - off] : 0u;
            __syncthreads();
            s_scan[t] += x;
            __syncthreads();
        }
        unsigned int nid = L_ + s_base + s_scan[t] - c;
        unsigned int tot = s_scan[BT - 1];
        #pragma unroll
        for (int i = 0; i < EPT; i++) {
            if (st[i] == 2) {
                g_nid[lo + t * EPT + i] = nid;
                g_alt[nid] = __uint_as_float(wb[i]);
                nid++;
            }
        }
        __syncthreads();
        if (t == 0) s_base += tot;
        __syncthreads();
    }
}

// ---------------- post: derive parent links from merge records ----------------
__global__ void k_hist(int M) {
    int k = blockIdx.x * blockDim.x + threadIdx.x;
    if (k >= M || g_nid[k] == 0xFFFFFFFFu) return;
    unsigned int rec = g_rec[k];
    atomicAdd(&g_cnt[rec >> 16], 1u);
    atomicAdd(&g_cnt[rec & 0xFFFFu], 1u);
}

__global__ void k_offscan() {
    __shared__ unsigned int s[1024];
    __shared__ unsigned int s_run;
    int t = threadIdx.x;
    if (t == 0) s_run = 0u;
    __syncthreads();
    for (int c = 0; c < L_ / 1024; c++) {
        unsigned int x = g_cnt[c * 1024 + t];
        s[t] = x;
        __syncthreads();
        for (int off = 1; off < 1024; off <<= 1) {
            unsigned int y = (t >= off) ? s[t - off] : 0u;
            __syncthreads();
            s[t] += y;
            __syncthreads();
        }
        unsigned int run = s_run;
        g_offs[c * 1024 + t] = run + s[t] - x;   // exclusive
        g_cnt[c * 1024 + t] = 0u;                // reset as scatter cursor
        unsigned int tot = s[1023];
        __syncthreads();
        if (t == 0) s_run = run + tot;
        __syncthreads();
    }
}

__global__ void k_scatter(int M) {
    int k = blockIdx.x * blockDim.x + threadIdx.x;
    if (k >= M || g_nid[k] == 0xFFFFFFFFu) return;
    unsigned int rec = g_rec[k];
    unsigned int w = rec >> 16, l = rec & 0xFFFFu;
    g_evt[g_offs[w] + atomicAdd(&g_cnt[w], 1u)] = (unsigned int)k;
    g_evt[g_offs[l] + atomicAdd(&g_cnt[l], 1u)] = (unsigned int)k;
}

__global__ void k_vlink() {
    int v = blockIdx.x * blockDim.x + threadIdx.x;
    if (v >= L_) return;
    unsigned int n = g_cnt[v], base = g_offs[v];
    if (n == 0) return;
    // selection sort (lists avg 2, max ~tree depth)
    for (unsigned int i = 0; i + 1 < n; i++) {
        unsigned int mi = i, mv = g_evt[base + i];
        for (unsigned int j = i + 1; j < n; j++) {
            unsigned int x = g_evt[base + j];
            if (x < mv) { mv = x; mi = j; }
        }
        if (mi != i) { g_evt[base + mi] = g_evt[base + i]; g_evt[base + i] = mv; }
    }
    // chain: leaf -> first event; node(e_t) -> node(e_{t+1})
    unsigned int prev = g_nid[g_evt[base]];
    g_parent[v] = prev;
    for (unsigned int i = 1; i < n; i++) {
        unsigned int cur = g_nid[g_evt[base + i]];
        g_parent[prev] = cur;
        prev = cur;
    }
}

__global__ void k_sizes() {
    int v = blockIdx.x * blockDim.x + threadIdx.x;
    if (v >= L_) return;
    unsigned int p = g_parent[v];
    for (;;) {
        atomicAdd(&g_sizes[p], 1.0f);
        unsigned int q = g_parent[p];
        if (q == p) break;
        p = q;
    }
}

// ---------------- softarea (validated in round 1) ----------------
__global__ void k_zero(float* __restrict__ out) {
    int i = blockIdx.x * blockDim.x + threadIdx.x;
    if (i < NN) out[i] = 0.0f;
}

__device__ __forceinline__ float sigm(float x) {
    return 1.0f / (1.0f + __expf(-x));   // LAM = 1
}

__global__ void k_softarea(float* __restrict__ out) {
    int n = blockIdx.x * blockDim.x + threadIdx.x;
    if (n >= NN) return;

    float altn = g_alt[n];
    float outside = 0.0f;
    unsigned int c = (unsigned int)n;
    float szc = g_sizes[c];
    for (;;) {
        unsigned int p = g_parent[c];
        if (p == c) break;
        float szp = g_sizes[p];
        outside += (szp - szc) * sigm(altn - g_alt[p]);
        c = p; szc = szp;
    }

    float self = outside;
    if (n < L_) {
        self += 0.5f;
        unsigned int a = g_parent[n];
        float alt1 = g_alt[a];
        for (;;) {
            atomicAdd(&out[a], sigm(g_alt[a] - alt1));
            unsigned int pa = g_parent[a];
            if (pa == a) break;
            a = pa;
        }
    }
    atomicAdd(&out[n], self);
}

// ---------------- launch ----------------
extern "C" void kernel_launch(void* const* d_in, const int* in_sizes, int n_in,
                              void* d_out, int out_size) {
    const float* ew  = (const float*)d_in[0];
    const int*   src = (const int*)d_in[1];
    const int*   dst = (const int*)d_in[2];
    int M = in_sizes[0];   // 130560

    k_init<<<NPAD / 256, 256>>>(ew, M);

    k_bitonic_local_init<<<NPAD / 2048, 1024>>>();
    for (int k = 4096; k <= NPAD; k <<= 1) {
        for (int j = k >> 1; j >= 2048; j >>= 1)
            k_bitonic_global<<<(NPAD / 2) / 256, 256>>>(j, k);
        k_bitonic_local_tail<<<NPAD / 2048, 1024>>>(k);
    }

    k_build<<<1, BT>>>(src, dst, M);

    k_hist<<<(M + 255) / 256, 256>>>(M);
    k_offscan<<<1, 1024>>>();
    k_scatter<<<(M + 255) / 256, 256>>>(M);
    k_vlink<<<(L_ + 255) / 256, 256>>>();
    k_sizes<<<(L_ + 255) / 256, 256>>>();

    float* out = (float*)d_out;
    k_zero<<<(NN + 255) / 256, 256>>>(out);
    k_softarea<<<(NN + 255) / 256, 256>>>(out);
}

// round 3
// speedup vs baseline: 1.2056x; 1.0669x over previous
#include <cuda_runtime.h>
#include <cstdint>

// Problem constants (256x256 grid, 4-adjacency)
#define L_    65536      // leaves
#define NN    131071     // 2L-1 nodes
#define NPAD  262144     // 2^18 >= 130560 edges
#define MMAX  130560
#define BT    1024       // build-kernel threads
#define EPT   4          // edges per thread per round
#define BRND  (BT*EPT)   // 4096 edges per round

// ---------------- device scratch ----------------
__device__ unsigned long long g_keys[NPAD];  // (wbits<<32)|edge_idx, sorted asc
__device__ unsigned int g_mark[L_];          // version-stamped min-edge marks (per root vertex)
__device__ unsigned int g_size[L_];          // component size at UF root
__device__ unsigned short g_min[L_];         // component min-vertex at UF root
__device__ unsigned int g_rec[MMAX];         // accepted rank k -> (win_min<<16)|lose_min
__device__ unsigned int g_nid[MMAX];         // accepted rank k -> node id; ~0 = rejected
__device__ unsigned int g_parent[NN];
__device__ float        g_alt[NN];
__device__ float        g_sizes[NN];
__device__ unsigned int g_cnt[L_];           // per-vertex event counts / cursors
__device__ unsigned int g_offs[L_];
__device__ unsigned int g_evt[2 * (L_ - 1)]; // event ranks, grouped by vertex

// ---------------- init ----------------
__global__ void k_init(const float* __restrict__ ew, int M) {
    int i = blockIdx.x * blockDim.x + threadIdx.x;
    if (i < NPAD) {
        if (i < M) {
            unsigned int wb = __float_as_uint(ew[i]);  // weights in [0,1): bits monotone
            g_keys[i] = ((unsigned long long)wb << 32) | (unsigned int)i;
        } else {
            g_keys[i] = ~0ull;
        }
    }
    if (i < L_) {
        g_mark[i] = 0xFFFFFFFFu;
        g_size[i] = 1u;
        g_min[i]  = (unsigned short)i;
        g_cnt[i]  = 0u;
    }
    if (i < NN) { g_parent[i] = i; g_alt[i] = 0.0f; g_sizes[i] = (i < L_) ? 1.0f : 0.0f; }
    if (i < MMAX) g_nid[i] = 0xFFFFFFFFu;
}

// ---------------- bitonic sort (unique 64-bit keys => stability for free) ----------------
__global__ void k_bitonic_local_init() {
    __shared__ unsigned long long s[2048];
    int base = blockIdx.x * 2048;
    int t = threadIdx.x;
    s[t]        = g_keys[base + t];
    s[t + 1024] = g_keys[base + t + 1024];
    __syncthreads();
    for (int k = 2; k <= 2048; k <<= 1) {
        for (int j = k >> 1; j > 0; j >>= 1) {
            int pos = ((t & ~(j - 1)) << 1) | (t & (j - 1));
            int gi  = base + pos;
            bool asc = ((gi & k) == 0);
            unsigned long long x = s[pos], y = s[pos + j];
            if ((x > y) == asc) { s[pos] = y; s[pos + j] = x; }
            __syncthreads();
        }
    }
    g_keys[base + t]        = s[t];
    g_keys[base + t + 1024] = s[t + 1024];
}

__global__ void k_bitonic_global(int j, int k) {
    int t = blockIdx.x * blockDim.x + threadIdx.x;
    int i = ((t & ~(j - 1)) << 1) | (t & (j - 1));
    int l = i + j;
    bool asc = ((i & k) == 0);
    unsigned long long x = g_keys[i], y = g_keys[l];
    if ((x > y) == asc) { g_keys[i] = y; g_keys[l] = x; }
}

__global__ void k_bitonic_local_tail(int k) {
    __shared__ unsigned long long s[2048];
    int base = blockIdx.x * 2048;
    int t = threadIdx.x;
    s[t]        = g_keys[base + t];
    s[t + 1024] = g_keys[base + t + 1024];
    __syncthreads();
    bool asc = ((base & k) == 0);
    for (int j = 1024; j > 0; j >>= 1) {
        int pos = ((t & ~(j - 1)) << 1) | (t & (j - 1));
        unsigned long long x = s[pos], y = s[pos + j];
        if ((x > y) == asc) { s[pos] = y; s[pos + j] = x; }
        __syncthreads();
    }
    g_keys[base + t]        = s[t];
    g_keys[base + t + 1024] = s[t + 1024];
}

// ---------------- smem union-find (path halving; benign races; balanced by size) --------
__device__ __forceinline__ unsigned int uf_find_s(volatile unsigned short* uf, unsigned int x) {
    for (;;) {
        unsigned int p = uf[x];
        if (p == x) return x;
        unsigned int gp = uf[p];
        if (gp == p) return p;
        uf[x] = (unsigned short)gp;
        x = gp;
    }
}

__device__ __forceinline__ unsigned int ldcg_u32(const unsigned int* p) {
    unsigned int v;
    asm volatile("ld.global.cg.u32 %0, [%1];" : "=r"(v) : "l"(p));
    return v;
}

// ---------------- batched-parallel Kruskal (single block, UF in smem) ----------------
__global__ void k_build(const int* __restrict__ src, const int* __restrict__ dst, int M) {
    extern __shared__ unsigned short s_uf[];   // 65536 x u16 = 128KB
    __shared__ unsigned int s_scan[BT];
    __shared__ unsigned int s_flag, s_ver, s_base;
    int t = threadIdx.x;

    for (int v = t; v < L_; v += BT) s_uf[v] = (unsigned short)v;
    if (t == 0) { s_ver = 0u; s_base = 0u; }
    __syncthreads();

    int nrounds = (M + BRND - 1) / BRND;
    for (int r = 0; r < nrounds; r++) {
        int lo = r * BRND;
        unsigned int av[EPT], bv[EPT], wb[EPT];
        int st[EPT];   // 0=active 1=done(rejected/pad) 2=accepted
        #pragma unroll
        for (int i = 0; i < EPT; i++) {
            int e = lo + t * EPT + i;
            if (e < M) {
                unsigned long long key = g_keys[e];
                unsigned int idx = (unsigned int)key;
                av[i] = (unsigned int)src[idx];
                bv[i] = (unsigned int)dst[idx];
                wb[i] = (unsigned int)(key >> 32);
                st[i] = 0;
            } else st[i] = 1;
        }

        for (;;) {
            __syncthreads();
            if (t == 0) { s_flag = 0u; s_ver++; }
            __syncthreads();
            unsigned int ver = s_ver;   // global version, never reset

            // mark phase: min (by within-round rank) live edge marks both its roots
            #pragma unroll
            for (int i = 0; i < EPT; i++) {
                if (st[i] == 0) {
                    unsigned int a = uf_find_s(s_uf, av[i]);
                    unsigned int b = uf_find_s(s_uf, bv[i]);
                    if (a == b) { st[i] = 1; continue; }   // rejected forever
                    av[i] = a; bv[i] = b;
                    unsigned int pk = ((0xFFFFFu - ver) << 12) | (unsigned int)(t * EPT + i);
                    atomicMin(&g_mark[a], pk);
                    atomicMin(&g_mark[b], pk);
                }
            }
            __syncthreads();

            // commit phase: commit iff min-holder on BOTH roots (roots pairwise disjoint)
            bool rem = false;
            #pragma unroll
            for (int i = 0; i < EPT; i++) {
                if (st[i] == 0) {
                    unsigned int pk = ((0xFFFFFu - ver) << 12) | (unsigned int)(t * EPT + i);
                    // marks were set by atomics (L2) -> bypass L1 on read
                    if (ldcg_u32(&g_mark[av[i]]) == pk && ldcg_u32(&g_mark[bv[i]]) == pk) {
                        unsigned int a = av[i], b = bv[i];
                        unsigned int sa = g_size[a], sb = g_size[b];
                        unsigned int big = (sa >= sb) ? a : b;
                        unsigned int sml = (sa >= sb) ? b : a;
                        s_uf[sml] = (unsigned short)big;       // union by size
                        g_size[big] = sa + sb;
                        unsigned int ma = g_min[a], mb = g_min[b];
                        unsigned int w = ma < mb ? ma : mb;
                        unsigned int l = ma < mb ? mb : ma;
                        g_min[big] = (unsigned short)w;
                        g_rec[lo + t * EPT + i] = (w << 16) | l;
                        st[i] = 2;
                    } else rem = true;
                }
            }
            if (rem) s_flag = 1u;
            __syncthreads();
            if (s_flag == 0u) break;
        }

        // round-end: assign node ids in rank order (block inclusive scan)
        unsigned int c = 0;
        #pragma unroll
        for (int i = 0; i < EPT; i++) if (st[i] == 2) c++;
        s_scan[t] = c;
        __syncthreads();
        for (int off = 1; off < BT; off <<= 1) {
            unsigned int x = (t >= off) ? s_scan[t - off] : 0u;
            __syncthreads();
            s_scan[t] += x;
            __syncthreads();
        }
        unsigned int nid = L_ + s_base + s_scan[t] - c;
        unsigned int tot = s_scan[BT - 1];
        #pragma unroll
        for (int i = 0; i < EPT; i++) {
            if (st[i] == 2) {
                g_nid[lo + t * EPT + i] = nid;
                g_alt[nid] = __uint_as_float(wb[i]);
                nid++;
            }
        }
        __syncthreads();
        if (t == 0) s_base += tot;
        __syncthreads();
    }
}

// ---------------- post: derive parent links from merge records ----------------
__global__ void k_hist(int M) {
    int k = blockIdx.x * blockDim.x + threadIdx.x;
    if (k >= M || g_nid[k] == 0xFFFFFFFFu) return;
    unsigned int rec = g_rec[k];
    atomicAdd(&g_cnt[rec >> 16], 1u);
    atomicAdd(&g_cnt[rec & 0xFFFFu], 1u);
}

__global__ void k_offscan() {
    __shared__ unsigned int s[1024];
    __shared__ unsigned int s_run;
    int t = threadIdx.x;
    if (t == 0) s_run = 0u;
    __syncthreads();
    for (int c = 0; c < L_ / 1024; c++) {
        unsigned int x = g_cnt[c * 1024 + t];
        s[t] = x;
        __syncthreads();
        for (int off = 1; off < 1024; off <<= 1) {
            unsigned int y = (t >= off) ? s[t - off] : 0u;
            __syncthreads();
            s[t] += y;
            __syncthreads();
        }
        unsigned int run = s_run;
        g_offs[c * 1024 + t] = run + s[t] - x;   // exclusive
        g_cnt[c * 1024 + t] = 0u;                // reset as scatter cursor
        unsigned int tot = s[1023];
        __syncthreads();
        if (t == 0) s_run = run + tot;
        __syncthreads();
    }
}

__global__ void k_scatter(int M) {
    int k = blockIdx.x * blockDim.x + threadIdx.x;
    if (k >= M || g_nid[k] == 0xFFFFFFFFu) return;
    unsigned int rec = g_rec[k];
    unsigned int w = rec >> 16, l = rec & 0xFFFFu;
    g_evt[g_offs[w] + atomicAdd(&g_cnt[w], 1u)] = (unsigned int)k;
    g_evt[g_offs[l] + atomicAdd(&g_cnt[l], 1u)] = (unsigned int)k;
}

__global__ void k_vlink() {
    int v = blockIdx.x * blockDim.x + threadIdx.x;
    if (v >= L_) return;
    unsigned int n = g_cnt[v], base = g_offs[v];
    if (n == 0) return;
    // selection sort (lists avg 2, max ~tree depth)
    for (unsigned int i = 0; i + 1 < n; i++) {
        unsigned int mi = i, mv = g_evt[base + i];
        for (unsigned int j = i + 1; j < n; j++) {
            unsigned int x = g_evt[base + j];
            if (x < mv) { mv = x; mi = j; }
        }
        if (mi != i) { g_evt[base + mi] = g_evt[base + i]; g_evt[base + i] = mv; }
    }
    // chain: leaf -> first event; node(e_t) -> node(e_{t+1})
    unsigned int prev = g_nid[g_evt[base]];
    g_parent[v] = prev;
    for (unsigned int i = 1; i < n; i++) {
        unsigned int cur = g_nid[g_evt[base + i]];
        g_parent[prev] = cur;
        prev = cur;
    }
}

__global__ void k_sizes() {
    int v = blockIdx.x * blockDim.x + threadIdx.x;
    if (v >= L_) return;
    unsigned int p = g_parent[v];
    for (;;) {
        atomicAdd(&g_sizes[p], 1.0f);
        unsigned int q = g_parent[p];
        if (q == p) break;
        p = q;
    }
}

// ---------------- softarea (validated) ----------------
__global__ void k_zero(float* __restrict__ out) {
    int i = blockIdx.x * blockDim.x + threadIdx.x;
    if (i < NN) out[i] = 0.0f;
}

__device__ __forceinline__ float sigm(float x) {
    return 1.0f / (1.0f + __expf(-x));   // LAM = 1
}

__global__ void k_softarea(float* __restrict__ out) {
    int n = blockIdx.x * blockDim.x + threadIdx.x;
    if (n >= NN) return;

    float altn = g_alt[n];
    float outside = 0.0f;
    unsigned int c = (unsigned int)n;
    float szc = g_sizes[c];
    for (;;) {
        unsigned int p = g_parent[c];
        if (p == c) break;
        float szp = g_sizes[p];
        outside += (szp - szc) * sigm(altn - g_alt[p]);
        c = p; szc = szp;
    }

    float self = outside;
    if (n < L_) {
        self += 0.5f;
        unsigned int a = g_parent[n];
        float alt1 = g_alt[a];
        for (;;) {
            atomicAdd(&out[a], sigm(g_alt[a] - alt1));
            unsigned int pa = g_parent[a];
            if (pa == a) break;
            a = pa;
        }
    }
    atomicAdd(&out[n], self);
}

// ---------------- launch ----------------
extern "C" void kernel_launch(void* const* d_in, const int* in_sizes, int n_in,
                              void* d_out, int out_size) {
    const float* ew  = (const float*)d_in[0];
    const int*   src = (const int*)d_in[1];
    const int*   dst = (const int*)d_in[2];
    int M = in_sizes[0];   // 130560

    k_init<<<NPAD / 256, 256>>>(ew, M);

    k_bitonic_local_init<<<NPAD / 2048, 1024>>>();
    for (int k = 4096; k <= NPAD; k <<= 1) {
        for (int j = k >> 1; j >= 2048; j >>= 1)
            k_bitonic_global<<<(NPAD / 2) / 256, 256>>>(j, k);
        k_bitonic_local_tail<<<NPAD / 2048, 1024>>>(k);
    }

    // 128KB dynamic smem for the UF parent array
    cudaFuncSetAttribute(k_build, cudaFuncAttributeMaxDynamicSharedMemorySize, L_ * 2);
    k_build<<<1, BT, L_ * 2>>>(src, dst, M);

    k_hist<<<(M + 255) / 256, 256>>>(M);
    k_offscan<<<1, 1024>>>();
    k_scatter<<<(M + 255) / 256, 256>>>(M);
    k_vlink<<<(L_ + 255) / 256, 256>>>();
    k_sizes<<<(L_ + 255) / 256, 256>>>();

    float* out = (float*)d_out;
    k_zero<<<(NN + 255) / 256, 256>>>(out);
    k_softarea<<<(NN + 255) / 256, 256>>>(out);
}

// round 5
// speedup vs baseline: 1.2841x; 1.0652x over previous
#include <cuda_runtime.h>
#include <cstdint>

// Problem constants (256x256 grid, 4-adjacency)
#define L_    65536      // leaves
#define NN    131071     // 2L-1 nodes
#define NPAD  262144     // 2^18 >= 130560 edges
#define MACC  (L_ - 1)   // accepted merges = 65535
#define FULLM 0xFFFFFFFFu

// ---------------- device scratch ----------------
__device__ unsigned long long g_keys[NPAD];   // (wbits<<32)|edge_idx, sorted asc
__device__ unsigned long long g_esort[NPAD];  // (wbits<<32)|(v<<16)|u in rank order
__device__ unsigned int g_rec[MACC];          // accepted i -> (win_min<<16)|lose_min
__device__ unsigned int g_parent[NN];
__device__ float        g_alt[NN];
__device__ float        g_sizes[NN];
__device__ unsigned int g_cnt[L_];
__device__ unsigned int g_offs[L_];
__device__ unsigned int g_evt[2 * MACC];

// ---------------- init ----------------
__global__ void k_init(const float* __restrict__ ew, int M) {
    int i = blockIdx.x * blockDim.x + threadIdx.x;
    if (i < NPAD) {
        if (i < M) {
            unsigned int wb = __float_as_uint(ew[i]);  // weights in [0,1): bits monotone
            g_keys[i] = ((unsigned long long)wb << 32) | (unsigned int)i;
        } else {
            g_keys[i] = ~0ull;
        }
    }
    if (i < L_) g_cnt[i] = 0u;
    if (i < NN) { g_parent[i] = i; g_alt[i] = 0.0f; g_sizes[i] = (i < L_) ? 1.0f : 0.0f; }
}

// ---------------- bitonic sort (unique 64-bit keys => stability for free) ----------------
__global__ void k_bitonic_local_init() {
    __shared__ unsigned long long s[2048];
    int base = blockIdx.x * 2048;
    int t = threadIdx.x;
    s[t]        = g_keys[base + t];
    s[t + 1024] = g_keys[base + t + 1024];
    __syncthreads();
    for (int k = 2; k <= 2048; k <<= 1) {
        for (int j = k >> 1; j > 0; j >>= 1) {
            int pos = ((t & ~(j - 1)) << 1) | (t & (j - 1));
            int gi  = base + pos;
            bool asc = ((gi & k) == 0);
            unsigned long long x = s[pos], y = s[pos + j];
            if ((x > y) == asc) { s[pos] = y; s[pos + j] = x; }
            __syncthreads();
        }
    }
    g_keys[base + t]        = s[t];
    g_keys[base + t + 1024] = s[t + 1024];
}

__global__ void k_bitonic_global(int j, int k) {
    int t = blockIdx.x * blockDim.x + threadIdx.x;
    int i = ((t & ~(j - 1)) << 1) | (t & (j - 1));
    int l = i + j;
    bool asc = ((i & k) == 0);
    unsigned long long x = g_keys[i], y = g_keys[l];
    if ((x > y) == asc) { g_keys[i] = y; g_keys[l] = x; }
}

__global__ void k_bitonic_local_tail(int k) {
    __shared__ unsigned long long s[2048];
    int base = blockIdx.x * 2048;
    int t = threadIdx.x;
    s[t]        = g_keys[base + t];
    s[t + 1024] = g_keys[base + t + 1024];
    __syncthreads();
    bool asc = ((base & k) == 0);
    for (int j = 1024; j > 0; j >>= 1) {
        int pos = ((t & ~(j - 1)) << 1) | (t & (j - 1));
        unsigned long long x = s[pos], y = s[pos + j];
        if ((x > y) == asc) { s[pos] = y; s[pos + j] = x; }
        __syncthreads();
    }
    g_keys[base + t]        = s[t];
    g_keys[base + t + 1024] = s[t + 1024];
}

// ---------------- gather sorted edge endpoints into one stream ----------------
__global__ void k_gather(const int* __restrict__ src, const int* __restrict__ dst, int M) {
    int e = blockIdx.x * blockDim.x + threadIdx.x;
    if (e >= NPAD) return;
    if (e < M) {
        unsigned long long key = g_keys[e];
        unsigned int idx = (unsigned int)(key & 0xFFFFFFFFull);
        unsigned int wb  = (unsigned int)(key >> 32);
        unsigned int u = (unsigned int)src[idx];
        unsigned int v = (unsigned int)dst[idx];
        g_esort[e] = ((unsigned long long)wb << 32) | (v << 16) | u;
    } else {
        g_esort[e] = 0ull;   // pad: u==v==0 -> rejected in replay
    }
}

// ---------------- single-warp windowed Kruskal replay ----------------
// UF: union-by-min + full path compression => root == component min.
__device__ __forceinline__ unsigned int uf_find(volatile unsigned short* uf, unsigned int x) {
    unsigned int r = x, p;
    while ((p = uf[r]) != r) r = p;            // find root
    while ((p = uf[x]) != r) {                 // full compression
        uf[x] = (unsigned short)r;
        x = p;
    }
    return r;
}

__global__ void k_replay(int M) {
    extern __shared__ unsigned short s_uf[];   // 65536 x u16 = 128KB
    __shared__ unsigned int s_roots[64];
    int lane = threadIdx.x;

    unsigned int* uf32 = (unsigned int*)s_uf;
    for (int i = lane; i < L_ / 2; i += 32)
        uf32[i] = (2u * i) | ((2u * i + 1u) << 16);
    __syncwarp();

    int nwin = (M + 31) / 32;
    unsigned int base_acc = 0;
    unsigned long long nxt  = g_esort[lane];
    unsigned long long nxt2 = g_esort[32 + lane];
    for (int w = 0; w < nwin; w++) {
        unsigned long long cur = nxt;
        nxt = nxt2;
        if (w + 2 < nwin) nxt2 = g_esort[(w + 2) * 32 + lane];

        unsigned int u  = (unsigned int)cur & 0xFFFFu;
        unsigned int v  = ((unsigned int)cur >> 16) & 0xFFFFu;
        unsigned int wb = (unsigned int)(cur >> 32);

        // speculative parallel finds (only compression writes race: safe)
        unsigned int a = uf_find(s_uf, u);
        unsigned int b = uf_find(s_uf, v);
        bool alive = (a != b);                 // monotone: a==b is final rejection
        s_roots[2 * lane]     = alive ? a : FULLM;
        s_roots[2 * lane + 1] = alive ? b : FULLM;
        __syncwarp();

        // conflict: shares a root with any EARLIER alive lane
        bool conflict = false;
        if (alive) {
            for (int j = 0; j < 2 * lane; j++) {
                unsigned int r = s_roots[j];
                conflict |= (r == a || r == b);
            }
        }
        unsigned int chain = __ballot_sync(FULLM, alive && conflict);

        // parallel commits: pairwise-disjoint roots => race-free, order-irrelevant.
        // Records buffered in registers; slots assigned at window end in LANE
        // (= rank) order, so node ids match the reference numbering.
        bool acc = false;
        unsigned int rec = 0;
        if (alive && !conflict) {
            unsigned int wmn = a < b ? a : b;
            unsigned int lmx = a < b ? b : a;
            s_uf[lmx] = (unsigned short)wmn;
            rec = (wmn << 16) | lmx;
            acc = true;
        }
        __syncwarp();

        // serial chain: in rank (lane) order, cheap smem refind per step
        while (chain) {
            int j = __ffs(chain) - 1;
            chain &= chain - 1;
            if (lane == j) {
                a = uf_find(s_uf, u);
                b = uf_find(s_uf, v);
                if (a != b) {
                    unsigned int wmn = a < b ? a : b;
                    unsigned int lmx = a < b ? b : a;
                    s_uf[lmx] = (unsigned short)wmn;
                    rec = (wmn << 16) | lmx;
                    acc = true;
                }
            }
            __syncwarp();
        }

        // rank-ordered slot assignment (lane order == sorted-edge order)
        unsigned int ab = __ballot_sync(FULLM, acc);
        if (acc) {
            unsigned int slot = base_acc + __popc(ab & ((1u << lane) - 1u));
            g_rec[slot]      = rec;
            g_alt[L_ + slot] = __uint_as_float(wb);
        }
        base_acc += __popc(ab);
    }
}

// ---------------- post: derive parent links from merge records ----------------
__global__ void k_hist() {
    int k = blockIdx.x * blockDim.x + threadIdx.x;
    if (k >= MACC) return;
    unsigned int rec = g_rec[k];
    atomicAdd(&g_cnt[rec >> 16], 1u);
    atomicAdd(&g_cnt[rec & 0xFFFFu], 1u);
}

__global__ void k_offscan() {
    __shared__ unsigned int s[1024];
    __shared__ unsigned int s_run;
    int t = threadIdx.x;
    if (t == 0) s_run = 0u;
    __syncthreads();
    for (int c = 0; c < L_ / 1024; c++) {
        unsigned int x = g_cnt[c * 1024 + t];
        s[t] = x;
        __syncthreads();
        for (int off = 1; off < 1024; off <<= 1) {
            unsigned int y = (t >= off) ? s[t - off] : 0u;
            __syncthreads();
            s[t] += y;
            __syncthreads();
        }
        unsigned int run = s_run;
        g_offs[c * 1024 + t] = run + s[t] - x;   // exclusive
        g_cnt[c * 1024 + t] = 0u;                // reset as scatter cursor
        unsigned int tot = s[1023];
        __syncthreads();
        if (t == 0) s_run = run + tot;
        __syncthreads();
    }
}

__global__ void k_scatter() {
    int k = blockIdx.x * blockDim.x + threadIdx.x;
    if (k >= MACC) return;
    unsigned int rec = g_rec[k];
    unsigned int w = rec >> 16, l = rec & 0xFFFFu;
    g_evt[g_offs[w] + atomicAdd(&g_cnt[w], 1u)] = (unsigned int)k;
    g_evt[g_offs[l] + atomicAdd(&g_cnt[l], 1u)] = (unsigned int)k;
}

__global__ void k_vlink() {
    int v = blockIdx.x * blockDim.x + threadIdx.x;
    if (v >= L_) return;
    unsigned int n = g_cnt[v], base = g_offs[v];
    if (n == 0) return;
    for (unsigned int i = 0; i + 1 < n; i++) {       // selection sort, avg n=2
        unsigned int mi = i, mv = g_evt[base + i];
        for (unsigned int j = i + 1; j < n; j++) {
            unsigned int x = g_evt[base + j];
            if (x < mv) { mv = x; mi = j; }
        }
        if (mi != i) { g_evt[base + mi] = g_evt[base + i]; g_evt[base + i] = mv; }
    }
    unsigned int prev = L_ + g_evt[base];
    g_parent[v] = prev;
    for (unsigned int i = 1; i < n; i++) {
        unsigned int curn = L_ + g_evt[base + i];
        g_parent[prev] = curn;
        prev = curn;
    }
}

// sizes via leaf->root walks with warp-level walker merging (counts are additive)
__global__ void k_sizes() {
    int v = blockIdx.x * blockDim.x + threadIdx.x;
    bool active = (v < L_);
    unsigned int node = active ? g_parent[v] : FULLM;
    int cnt = 1;
    while (__any_sync(FULLM, active)) {
        unsigned int key = active ? node : FULLM;
        unsigned int m = __match_any_sync(FULLM, key);
        int tot = __reduce_add_sync(m, active ? cnt : 0);
        int leader = __ffs(m) - 1;
        if (active) {
            if ((threadIdx.x & 31) == leader) {
                atomicAdd(&g_sizes[node], (float)tot);
                cnt = tot;
                unsigned int p = g_parent[node];
                if (p == node) active = false; else node = p;
            } else {
                active = false;   // absorbed into leader
            }
        }
    }
}

// ---------------- softarea (validated) ----------------
__global__ void k_zero(float* __restrict__ out) {
    int i = blockIdx.x * blockDim.x + threadIdx.x;
    if (i < NN) out[i] = 0.0f;
}

__device__ __forceinline__ float sigm(float x) {
    return 1.0f / (1.0f + __expf(-x));   // LAM = 1
}

__global__ void k_softarea(float* __restrict__ out) {
    int n = blockIdx.x * blockDim.x + threadIdx.x;
    if (n >= NN) return;

    float altn = g_alt[n];
    float outside = 0.0f;
    unsigned int c = (unsigned int)n;
    float szc = g_sizes[c];
    for (;;) {
        unsigned int p = g_parent[c];
        if (p == c) break;
        float szp = g_sizes[p];
        outside += (szp - szc) * sigm(altn - g_alt[p]);
        c = p; szc = szp;
    }

    float self = outside;
    if (n < L_) {
        self += 0.5f;
        unsigned int a = g_parent[n];
        float alt1 = g_alt[a];
        for (;;) {
            atomicAdd(&out[a], sigm(g_alt[a] - alt1));
            unsigned int pa = g_parent[a];
            if (pa == a) break;
            a = pa;
        }
    }
    atomicAdd(&out[n], self);
}

// ---------------- launch ----------------
extern "C" void kernel_launch(void* const* d_in, const int* in_sizes, int n_in,
                              void* d_out, int out_size) {
    const float* ew  = (const float*)d_in[0];
    const int*   src = (const int*)d_in[1];
    const int*   dst = (const int*)d_in[2];
    int M = in_sizes[0];   // 130560

    k_init<<<NPAD / 256, 256>>>(ew, M);

    k_bitonic_local_init<<<NPAD / 2048, 1024>>>();
    for (int k = 4096; k <= NPAD; k <<= 1) {
        for (int j = k >> 1; j >= 2048; j >>= 1)
            k_bitonic_global<<<(NPAD / 2) / 256, 256>>>(j, k);
        k_bitonic_local_tail<<<NPAD / 2048, 1024>>>(k);
    }

    k_gather<<<NPAD / 256, 256>>>(src, dst, M);

    cudaFuncSetAttribute(k_replay, cudaFuncAttributeMaxDynamicSharedMemorySize, L_ * 2);
    k_replay<<<1, 32, L_ * 2>>>(M);

    k_hist<<<(MACC + 255) / 256, 256>>>();
    k_offscan<<<1, 1024>>>();
    k_scatter<<<(MACC + 255) / 256, 256>>>();
    k_vlink<<<(L_ + 255) / 256, 256>>>();
    k_sizes<<<(L_ + 255) / 256, 256>>>();

    float* out = (float*)d_out;
    k_zero<<<(NN + 255) / 256, 256>>>(out);
    k_softarea<<<(NN + 255) / 256, 256>>>(out);
}

// round 6
// speedup vs baseline: 1.9215x; 1.4964x over previous
#include <cuda_runtime.h>
#include <cstdint>

// Problem constants (256x256 grid, 4-adjacency)
#define L_    65536      // leaves
#define NN    131071     // 2L-1 nodes
#define NPAD  262144     // 2^18 >= 130560 edges
#define MACC  (L_ - 1)   // accepted merges = 65535
#define FULLM 0xFFFFFFFFu
#define ELEN  (2 * NN)   // Euler elements = 262142
#define ESENT ELEN       // sentinel element
#define EP    262144     // Euler plane stride (pow2 >= ELEN)
#define NILN  NN         // sentinel node for jump pointers

// ---------------- device scratch ----------------
__device__ unsigned long long g_keys[NPAD];
__device__ unsigned long long g_esort[NPAD];
__device__ unsigned int g_rec[MACC];          // accepted i -> (win_min<<16)|lose_min
__device__ unsigned int g_parent[NN];
__device__ float        g_alt[NN];
__device__ float        g_sizes[NN];
__device__ unsigned int g_cnt[L_];
__device__ unsigned int g_offs[L_];
__device__ unsigned int g_evt[2 * MACC];
__device__ unsigned int g_chw[MACC];          // child node on win-min side
__device__ unsigned int g_chl[MACC];          // child node on lose-min side
__device__ unsigned int g_nx[2][ELEN + 1];    // Euler next ptr (ping-pong)
__device__ unsigned int g_dd[2][ELEN + 1];    // distance-to-end (ping-pong)
__device__ unsigned int g_pos[ELEN];          // Euler position
__device__ float        g_ev[10 * EP];        // Euler value planes (moments 0..9)
__device__ float        g_part[10 * 256];     // scan block partials
__device__ float        g_ins[NN];            // inside(a) for internal nodes
__device__ float        g_R[2][(NN + 1) * 12]; // path-sum vectors (10 used, pad 12)
__device__ unsigned int g_j[2][NN + 1];       // jump pointers

// ---------------- init ----------------
__global__ void k_init(const float* __restrict__ ew, int M) {
    int i = blockIdx.x * blockDim.x + threadIdx.x;
    if (i < NPAD) {
        if (i < M) {
            unsigned int wb = __float_as_uint(ew[i]);  // weights in [0,1): bits monotone
            g_keys[i] = ((unsigned long long)wb << 32) | (unsigned int)i;
        } else {
            g_keys[i] = ~0ull;
        }
    }
    if (i < L_) g_cnt[i] = 0u;
    if (i < NN) { g_parent[i] = i; g_alt[i] = 0.0f; g_sizes[i] = (i < L_) ? 1.0f : 0.0f; }
}

// ---------------- bitonic sort (unique 64-bit keys => stability for free) ---------------
__global__ void k_bitonic_local_init() {
    __shared__ unsigned long long s[2048];
    int base = blockIdx.x * 2048;
    int t = threadIdx.x;
    s[t]        = g_keys[base + t];
    s[t + 1024] = g_keys[base + t + 1024];
    __syncthreads();
    for (int k = 2; k <= 2048; k <<= 1) {
        for (int j = k >> 1; j > 0; j >>= 1) {
            int pos = ((t & ~(j - 1)) << 1) | (t & (j - 1));
            int gi  = base + pos;
            bool asc = ((gi & k) == 0);
            unsigned long long x = s[pos], y = s[pos + j];
            if ((x > y) == asc) { s[pos] = y; s[pos + j] = x; }
            __syncthreads();
        }
    }
    g_keys[base + t]        = s[t];
    g_keys[base + t + 1024] = s[t + 1024];
}

__global__ void k_bitonic_global(int j, int k) {
    int t = blockIdx.x * blockDim.x + threadIdx.x;
    int i = ((t & ~(j - 1)) << 1) | (t & (j - 1));
    int l = i + j;
    bool asc = ((i & k) == 0);
    unsigned long long x = g_keys[i], y = g_keys[l];
    if ((x > y) == asc) { g_keys[i] = y; g_keys[l] = x; }
}

__global__ void k_bitonic_local_tail(int k) {
    __shared__ unsigned long long s[2048];
    int base = blockIdx.x * 2048;
    int t = threadIdx.x;
    s[t]        = g_keys[base + t];
    s[t + 1024] = g_keys[base + t + 1024];
    __syncthreads();
    bool asc = ((base & k) == 0);
    for (int j = 1024; j > 0; j >>= 1) {
        int pos = ((t & ~(j - 1)) << 1) | (t & (j - 1));
        unsigned long long x = s[pos], y = s[pos + j];
        if ((x > y) == asc) { s[pos] = y; s[pos + j] = x; }
        __syncthreads();
    }
    g_keys[base + t]        = s[t];
    g_keys[base + t + 1024] = s[t + 1024];
}

// ---------------- gather sorted edge endpoints ----------------
__global__ void k_gather(const int* __restrict__ src, const int* __restrict__ dst, int M) {
    int e = blockIdx.x * blockDim.x + threadIdx.x;
    if (e >= NPAD) return;
    if (e < M) {
        unsigned long long key = g_keys[e];
        unsigned int idx = (unsigned int)(key & 0xFFFFFFFFull);
        unsigned int wb  = (unsigned int)(key >> 32);
        unsigned int u = (unsigned int)src[idx];
        unsigned int v = (unsigned int)dst[idx];
        g_esort[e] = ((unsigned long long)wb << 32) | (v << 16) | u;
    } else {
        g_esort[e] = 0ull;   // pad: u==v==0 -> rejected
    }
}

// ---------------- single-warp windowed Kruskal replay (validated round 5) --------------
__device__ __forceinline__ unsigned int uf_find(volatile unsigned short* uf, unsigned int x) {
    unsigned int r = x, p;
    while ((p = uf[r]) != r) r = p;
    while ((p = uf[x]) != r) { uf[x] = (unsigned short)r; x = p; }
    return r;
}

__global__ void k_replay(int M) {
    extern __shared__ unsigned short s_uf[];   // 65536 x u16 = 128KB
    __shared__ unsigned int s_roots[64];
    int lane = threadIdx.x;

    unsigned int* uf32 = (unsigned int*)s_uf;
    for (int i = lane; i < L_ / 2; i += 32)
        uf32[i] = (2u * i) | ((2u * i + 1u) << 16);
    __syncwarp();

    int nwin = (M + 31) / 32;
    unsigned int base_acc = 0;
    unsigned long long nxt  = g_esort[lane];
    unsigned long long nxt2 = g_esort[32 + lane];
    for (int w = 0; w < nwin; w++) {
        unsigned long long cur = nxt;
        nxt = nxt2;
        if (w + 2 < nwin) nxt2 = g_esort[(w + 2) * 32 + lane];

        unsigned int u  = (unsigned int)cur & 0xFFFFu;
        unsigned int v  = ((unsigned int)cur >> 16) & 0xFFFFu;
        unsigned int wb = (unsigned int)(cur >> 32);

        unsigned int a = uf_find(s_uf, u);
        unsigned int b = uf_find(s_uf, v);
        bool alive = (a != b);
        s_roots[2 * lane]     = alive ? a : FULLM;
        s_roots[2 * lane + 1] = alive ? b : FULLM;
        __syncwarp();

        bool conflict = false;
        if (alive) {
            for (int j = 0; j < 2 * lane; j++) {
                unsigned int r = s_roots[j];
                conflict |= (r == a || r == b);
            }
        }
        unsigned int chain = __ballot_sync(FULLM, alive && conflict);

        bool acc = false;
        unsigned int rec = 0;
        if (alive && !conflict) {
            unsigned int wmn = a < b ? a : b;
            unsigned int lmx = a < b ? b : a;
            s_uf[lmx] = (unsigned short)wmn;
            rec = (wmn << 16) | lmx;
            acc = true;
        }
        __syncwarp();

        while (chain) {
            int j = __ffs(chain) - 1;
            chain &= chain - 1;
            if (lane == j) {
                a = uf_find(s_uf, u);
                b = uf_find(s_uf, v);
                if (a != b) {
                    unsigned int wmn = a < b ? a : b;
                    unsigned int lmx = a < b ? b : a;
                    s_uf[lmx] = (unsigned short)wmn;
                    rec = (wmn << 16) | lmx;
                    acc = true;
                }
            }
            __syncwarp();
        }

        unsigned int ab = __ballot_sync(FULLM, acc);
        if (acc) {
            unsigned int slot = base_acc + __popc(ab & ((1u << lane) - 1u));
            g_rec[slot]      = rec;
            g_alt[L_ + slot] = __uint_as_float(wb);
        }
        base_acc += __popc(ab);
    }
}

// ---------------- derive parents + children from merge records ----------------
__global__ void k_hist() {
    int k = blockIdx.x * blockDim.x + threadIdx.x;
    if (k >= MACC) return;
    unsigned int rec = g_rec[k];
    atomicAdd(&g_cnt[rec >> 16], 1u);
    atomicAdd(&g_cnt[rec & 0xFFFFu], 1u);
}

__global__ void k_offscan() {
    __shared__ unsigned int s[1024];
    __shared__ unsigned int s_run;
    int t = threadIdx.x;
    if (t == 0) s_run = 0u;
    __syncthreads();
    for (int c = 0; c < L_ / 1024; c++) {
        unsigned int x = g_cnt[c * 1024 + t];
        s[t] = x;
        __syncthreads();
        for (int off = 1; off < 1024; off <<= 1) {
            unsigned int y = (t >= off) ? s[t - off] : 0u;
            __syncthreads();
            s[t] += y;
            __syncthreads();
        }
        unsigned int run = s_run;
        g_offs[c * 1024 + t] = run + s[t] - x;
        g_cnt[c * 1024 + t] = 0u;
        unsigned int tot = s[1023];
        __syncthreads();
        if (t == 0) s_run = run + tot;
        __syncthreads();
    }
}

__global__ void k_scatter() {
    int k = blockIdx.x * blockDim.x + threadIdx.x;
    if (k >= MACC) return;
    unsigned int rec = g_rec[k];
    unsigned int w = rec >> 16, l = rec & 0xFFFFu;
    g_evt[g_offs[w] + atomicAdd(&g_cnt[w], 1u)] = (unsigned int)k;
    g_evt[g_offs[l] + atomicAdd(&g_cnt[l], 1u)] = (unsigned int)k;
}

__global__ void k_vlink() {
    int v = blockIdx.x * blockDim.x + threadIdx.x;
    if (v >= L_) return;
    unsigned int n = g_cnt[v], base = g_offs[v];
    if (n == 0) return;
    for (unsigned int i = 0; i + 1 < n; i++) {       // selection sort, avg n=2
        unsigned int mi = i, mv = g_evt[base + i];
        for (unsigned int j = i + 1; j < n; j++) {
            unsigned int x = g_evt[base + j];
            if (x < mv) { mv = x; mi = j; }
        }
        if (mi != i) { g_evt[base + mi] = g_evt[base + i]; g_evt[base + i] = mv; }
    }
    unsigned int prevnode = (unsigned int)v;
    for (unsigned int i = 0; i < n; i++) {
        unsigned int e = g_evt[base + i];
        unsigned int node = L_ + e;
        g_parent[prevnode] = node;
        if ((g_rec[e] >> 16) == (unsigned int)v) g_chw[e] = prevnode;
        else                                     g_chl[e] = prevnode;
        prevnode = node;
    }
}

// ---------------- Euler tour construction + list ranking ----------------
// Elements: down(n) = n, up(n) = NN + n. Sentinel ESENT ends the list.
__global__ void k_euler() {
    int n = blockIdx.x * blockDim.x + threadIdx.x;
    if (n >= NN) return;
    if (n == 0) { g_nx[0][ESENT] = ESENT; g_dd[0][ESENT] = 0u; }
    g_dd[0][n]      = 1u;
    g_dd[0][NN + n] = 1u;
    if (n < L_) {
        g_nx[0][n] = NN + n;                 // down(leaf) -> up(leaf)
    } else {
        int k = n - L_;
        unsigned int cw = g_chw[k], cl = g_chl[k];
        g_nx[0][n] = cw;                     // down(n) -> down(cw)
        g_nx[0][NN + cw] = cl;               // up(cw)  -> down(cl)
        g_nx[0][NN + cl] = NN + n;           // up(cl)  -> up(n)
    }
    if (n == NN - 1) g_nx[0][NN + n] = ESENT;  // root's up -> end
}

__global__ void k_rank(int s) {   // one doubling round, ping-pong s -> 1-s
    int e = blockIdx.x * blockDim.x + threadIdx.x;
    if (e > ELEN) return;
    unsigned int nx = g_nx[s][e];
    g_dd[1 - s][e] = g_dd[s][e] + g_dd[s][nx];
    g_nx[1 - s][e] = g_nx[s][nx];
}

__global__ void k_pos(int fin) {
    int e = blockIdx.x * blockDim.x + threadIdx.x;
    if (e < ELEN) g_pos[e] = (unsigned int)ELEN - g_dd[fin][e];
}

// ---------------- Euler value planes: moments of altp(leaf) ----------------
__global__ void k_ezero() {
    int i = blockIdx.x * blockDim.x + threadIdx.x;
    if (i < 10 * EP) g_ev[i] = 0.0f;
}

__global__ void k_escatter() {
    int x = blockIdx.x * blockDim.x + threadIdx.x;
    if (x >= L_) return;
    unsigned int p = g_pos[x];                 // pos of down(leaf)
    float y = g_alt[g_parent[x]];
    float pw = 1.0f;
    #pragma unroll
    for (int i = 0; i < 10; i++) { g_ev[i * EP + p] = pw; pw *= y; }
}

// ---------------- 3-phase inclusive prefix scan over each plane ----------------
__global__ void k_scan1() {
    __shared__ float s[1024];
    int plane = blockIdx.y;
    int gi = blockIdx.x * 1024 + threadIdx.x;
    int t = threadIdx.x;
    float x = g_ev[plane * EP + gi];
    s[t] = x;
    __syncthreads();
    for (int off = 1; off < 1024; off <<= 1) {
        float y = (t >= off) ? s[t - off] : 0.0f;
        __syncthreads();
        s[t] += y;
        __syncthreads();
    }
    g_ev[plane * EP + gi] = s[t];
    if (t == 1023) g_part[plane * 256 + blockIdx.x] = s[1023];
}

__global__ void k_scan2() {
    __shared__ float s[256];
    int plane = blockIdx.y;
    int t = threadIdx.x;
    float x = g_part[plane * 256 + t];
    s[t] = x;
    __syncthreads();
    for (int off = 1; off < 256; off <<= 1) {
        float y = (t >= off) ? s[t - off] : 0.0f;
        __syncthreads();
        s[t] += y;
        __syncthreads();
    }
    g_part[plane * 256 + t] = s[t] - x;   // exclusive
}

__global__ void k_scan3() {
    int plane = blockIdx.y;
    int gi = blockIdx.x * 1024 + threadIdx.x;
    g_ev[plane * EP + gi] += g_part[plane * 256 + blockIdx.x];
}

// ---------------- sigmoid via degree-9 Taylor, binomial moment combine ----------------
// sum_terms sigma(x - y) = sum_m a_m B_m,  B_m = sum_i C(m,i) x^(m-i) (-1)^i A_i,
// where A_i = sum_terms (weight * y^i).
__device__ __forceinline__ float sig_combine(float x, const float* A) {
    float xp[10];
    xp[0] = 1.0f;
    #pragma unroll
    for (int p = 1; p < 10; p++) xp[p] = xp[p - 1] * x;
    float B0 = A[0];
    float B1 = xp[1] * A[0] - A[1];
    float B3 = xp[3] * A[0] - 3.0f * xp[2] * A[1] + 3.0f * xp[1] * A[2] - A[3];
    float B5 = xp[5] * A[0] - 5.0f * xp[4] * A[1] + 10.0f * xp[3] * A[2]
             - 10.0f * xp[2] * A[3] + 5.0f * xp[1] * A[4] - A[5];
    float B7 = xp[7] * A[0] - 7.0f * xp[6] * A[1] + 21.0f * xp[5] * A[2]
             - 35.0f * xp[4] * A[3] + 35.0f * xp[3] * A[4] - 21.0f * xp[2] * A[5]
             + 7.0f * xp[1] * A[6] - A[7];
    float B9 = xp[9] * A[0] - 9.0f * xp[8] * A[1] + 36.0f * xp[7] * A[2]
             - 84.0f * xp[6] * A[3] + 126.0f * xp[5] * A[4] - 126.0f * xp[4] * A[5]
             + 84.0f * xp[3] * A[6] - 36.0f * xp[2] * A[7] + 9.0f * xp[1] * A[8] - A[9];
    return 0.5f * B0 + 0.25f * B1 - 0.0208333333f * B3 + 0.0020833333f * B5
         - 2.1081349e-4f * B7 + 2.1357107e-5f * B9;
}

// ---------------- subtree moments -> sizes + inside ----------------
__global__ void k_subtree() {
    int k = blockIdx.x * blockDim.x + threadIdx.x;
    if (k >= MACC) return;
    int a = L_ + k;
    unsigned int pd = g_pos[a], pu = g_pos[NN + a];
    float T[10];
    #pragma unroll
    for (int i = 0; i < 10; i++) T[i] = g_ev[i * EP + pu] - g_ev[i * EP + pd];
    g_sizes[a] = T[0];
    g_ins[a] = sig_combine(g_alt[a], T);
}

// ---------------- ancestor path-sum doubling for outside ----------------
__global__ void k_rinit() {
    int n = blockIdx.x * blockDim.x + threadIdx.x;
    if (n > NN) return;
    if (n == NN) {                            // sentinel
        #pragma unroll
        for (int i = 0; i < 10; i++) g_R[0][n * 12 + i] = 0.0f;
        g_j[0][n] = NILN;
        return;
    }
    float sz = g_sizes[n];
    float x  = g_alt[n];
    unsigned int p = g_parent[n];
    bool isroot = (p == (unsigned int)n);
    float y = g_alt[p];
    float xp = 1.0f, yp = 1.0f;
    #pragma unroll
    for (int i = 0; i < 10; i++) {
        g_R[0][n * 12 + i] = sz * (xp - (isroot ? 0.0f : yp));
        xp *= x; yp *= y;
    }
    g_j[0][n] = isroot ? NILN : p;
}

__global__ void k_rdouble(int s) {
    int n = blockIdx.x * blockDim.x + threadIdx.x;
    if (n > NN) return;
    unsigned int j = g_j[s][n];
    #pragma unroll
    for (int i = 0; i < 10; i++)
        g_R[1 - s][n * 12 + i] = g_R[s][n * 12 + i] + g_R[s][j * 12 + i];
    g_j[1 - s][n] = g_j[s][j];
}

// ---------------- final: out = outside + (leaf ? 0.5 : inside) ----------------
__global__ void k_final(float* __restrict__ out, int fin) {
    int n = blockIdx.x * blockDim.x + threadIdx.x;
    if (n >= NN) return;
    float x  = g_alt[n];
    float sz = g_sizes[n];
    float A[10];
    float xp = 1.0f;
    #pragma unroll
    for (int i = 0; i < 10; i++) {
        A[i] = g_R[fin][n * 12 + i] - sz * xp;   // subtract u_i(n): strict ancestors only
        xp *= x;
    }
    float outside = sig_combine(x, A);
    out[n] = outside + (n < L_ ? 0.5f : g_ins[n]);
}

// ---------------- launch ----------------
extern "C" void kernel_launch(void* const* d_in, const int* in_sizes, int n_in,
                              void* d_out, int out_size) {
    const float* ew  = (const float*)d_in[0];
    const int*   src = (const int*)d_in[1];
    const int*   dst = (const int*)d_in[2];
    int M = in_sizes[0];   // 130560

    k_init<<<NPAD / 256, 256>>>(ew, M);

    k_bitonic_local_init<<<NPAD / 2048, 1024>>>();
    for (int k = 4096; k <= NPAD; k <<= 1) {
        for (int j = k >> 1; j >= 2048; j >>= 1)
            k_bitonic_global<<<(NPAD / 2) / 256, 256>>>(j, k);
        k_bitonic_local_tail<<<NPAD / 2048, 1024>>>(k);
    }

    k_gather<<<NPAD / 256, 256>>>(src, dst, M);

    cudaFuncSetAttribute(k_replay, cudaFuncAttributeMaxDynamicSharedMemorySize, L_ * 2);
    k_replay<<<1, 32, L_ * 2>>>(M);

    k_hist<<<(MACC + 255) / 256, 256>>>();
    k_offscan<<<1, 1024>>>();
    k_scatter<<<(MACC + 255) / 256, 256>>>();
    k_vlink<<<(L_ + 255) / 256, 256>>>();

    // Euler tour + list ranking (18 doubling rounds: 2^18 >= ELEN)
    k_euler<<<(NN + 255) / 256, 256>>>();
    int s = 0;
    for (int r = 0; r < 18; r++) {
        k_rank<<<(ELEN + 1 + 255) / 256, 256>>>(s);
        s = 1 - s;
    }
    k_pos<<<(ELEN + 255) / 256, 256>>>(s);

    // subtree moments via prefix scans over Euler order
    k_ezero<<<(10 * EP) / 256, 256>>>();
    k_escatter<<<(L_ + 255) / 256, 256>>>();
    {
        dim3 g1(256, 10); k_scan1<<<g1, 1024>>>();
        dim3 g2(1, 10);   k_scan2<<<g2, 256>>>();
        dim3 g3(256, 10); k_scan3<<<g3, 1024>>>();
    }
    k_subtree<<<(MACC + 255) / 256, 256>>>();

    // ancestor path sums via pointer doubling (17 rounds: 2^17 >= max depth)
    k_rinit<<<(NN + 1 + 255) / 256, 256>>>();
    int t = 0;
    for (int r = 0; r < 17; r++) {
        k_rdouble<<<(NN + 1 + 255) / 256, 256>>>(t);
        t = 1 - t;
    }

    k_final<<<(NN + 255) / 256, 256>>>((float*)d_out, t);
}

// round 7
// speedup vs baseline: 3.9590x; 2.0603x over previous
#include <cuda_runtime.h>
#include <cstdint>

// Problem constants (256x256 grid, 4-adjacency)
#define L_    65536      // leaves
#define NN    131071     // 2L-1 nodes
#define NPAD  262144     // 2^18 >= 130560 edges
#define MACC  (L_ - 1)   // accepted merges = 65535
#define FULLM 0xFFFFFFFFu
#define ELEN  (2 * NN)   // Euler elements = 262142
#define ESENT ELEN       // sentinel element
#define EP    262144     // Euler plane stride (pow2 >= ELEN)
#define NILN  NN         // sentinel node for jump pointers
#define CHUNK 1024       // edges per rank chunk
#define NCMAX 256

// ---------------- device scratch ----------------
__device__ unsigned long long g_keys[NPAD];
__device__ unsigned long long g_esort[NPAD];
__device__ unsigned int   g_uf[L_];           // phase-1 global UF (root = component min)
__device__ unsigned short g_lab[2 * NPAD];    // endpoint labels at chunk start
__device__ unsigned int   g_recTmp[NPAD];     // per-chunk records
__device__ unsigned int   g_srcTmp[NPAD];     // per-chunk source edge index
__device__ unsigned int   g_acnt[NCMAX];      // accepted per chunk
__device__ unsigned int   g_abase[NCMAX];     // exclusive scan of acnt
__device__ unsigned int g_rec[MACC];          // accepted i -> (win_min<<16)|lose_min
__device__ unsigned int g_parent[NN];
__device__ float        g_alt[NN];
__device__ float        g_sizes[NN];
__device__ unsigned int g_cnt[L_];
__device__ unsigned int g_offs[L_];
__device__ unsigned int g_evt[2 * MACC];
__device__ unsigned int g_chw[MACC];          // child node on win-min side
__device__ unsigned int g_chl[MACC];          // child node on lose-min side
__device__ unsigned int g_nx[2][ELEN + 1];    // Euler next ptr (ping-pong)
__device__ unsigned int g_dd[2][ELEN + 1];    // distance-to-end (ping-pong)
__device__ unsigned int g_pos[ELEN];          // Euler position
__device__ float        g_ev[10 * EP];        // Euler value planes (moments 0..9)
__device__ float        g_part[10 * 256];     // scan block partials
__device__ float        g_ins[NN];            // inside(a) for internal nodes
__device__ float        g_R[2][(NN + 1) * 12]; // path-sum vectors (10 used, pad 12)
__device__ unsigned int g_j[2][NN + 1];       // jump pointers

// ---------------- init ----------------
__global__ void k_init(const float* __restrict__ ew, int M) {
    int i = blockIdx.x * blockDim.x + threadIdx.x;
    if (i < NPAD) {
        if (i < M) {
            unsigned int wb = __float_as_uint(ew[i]);  // weights in [0,1): bits monotone
            g_keys[i] = ((unsigned long long)wb << 32) | (unsigned int)i;
        } else {
            g_keys[i] = ~0ull;
        }
    }
    if (i < L_) { g_cnt[i] = 0u; g_uf[i] = (unsigned int)i; }
    if (i < NN) { g_parent[i] = i; g_alt[i] = 0.0f; g_sizes[i] = (i < L_) ? 1.0f : 0.0f; }
}

// ---------------- bitonic sort (unique 64-bit keys => stability for free) ---------------
__global__ void k_bitonic_local_init() {
    __shared__ unsigned long long s[2048];
    int base = blockIdx.x * 2048;
    int t = threadIdx.x;
    s[t]        = g_keys[base + t];
    s[t + 1024] = g_keys[base + t + 1024];
    __syncthreads();
    for (int k = 2; k <= 2048; k <<= 1) {
        for (int j = k >> 1; j > 0; j >>= 1) {
            int pos = ((t & ~(j - 1)) << 1) | (t & (j - 1));
            int gi  = base + pos;
            bool asc = ((gi & k) == 0);
            unsigned long long x = s[pos], y = s[pos + j];
            if ((x > y) == asc) { s[pos] = y; s[pos + j] = x; }
            __syncthreads();
        }
    }
    g_keys[base + t]        = s[t];
    g_keys[base + t + 1024] = s[t + 1024];
}

__global__ void k_bitonic_global(int j, int k) {
    int t = blockIdx.x * blockDim.x + threadIdx.x;
    int i = ((t & ~(j - 1)) << 1) | (t & (j - 1));
    int l = i + j;
    bool asc = ((i & k) == 0);
    unsigned long long x = g_keys[i], y = g_keys[l];
    if ((x > y) == asc) { g_keys[i] = y; g_keys[l] = x; }
}

__global__ void k_bitonic_local_tail(int k) {
    __shared__ unsigned long long s[2048];
    int base = blockIdx.x * 2048;
    int t = threadIdx.x;
    s[t]        = g_keys[base + t];
    s[t + 1024] = g_keys[base + t + 1024];
    __syncthreads();
    bool asc = ((base & k) == 0);
    for (int j = 1024; j > 0; j >>= 1) {
        int pos = ((t & ~(j - 1)) << 1) | (t & (j - 1));
        unsigned long long x = s[pos], y = s[pos + j];
        if ((x > y) == asc) { s[pos] = y; s[pos + j] = x; }
        __syncthreads();
    }
    g_keys[base + t]        = s[t];
    g_keys[base + t + 1024] = s[t + 1024];
}

// ---------------- gather sorted edge endpoints ----------------
__global__ void k_gather(const int* __restrict__ src, const int* __restrict__ dst, int M) {
    int e = blockIdx.x * blockDim.x + threadIdx.x;
    if (e >= NPAD) return;
    if (e < M) {
        unsigned long long key = g_keys[e];
        unsigned int idx = (unsigned int)(key & 0xFFFFFFFFull);
        unsigned int wb  = (unsigned int)(key >> 32);
        unsigned int u = (unsigned int)src[idx];
        unsigned int v = (unsigned int)dst[idx];
        g_esort[e] = ((unsigned long long)wb << 32) | (v << 16) | u;
    } else {
        g_esort[e] = 0ull;
    }
}

// ---------------- phase 1: chunk-boundary labels via parallel UF (single block) --------
// Global UF; roots only ever point to smaller ids (CAS on roots) => root = component min.
__device__ __forceinline__ unsigned int gfind(unsigned int x) {
    unsigned int p;
    while ((p = g_uf[x]) != x) {
        unsigned int gp = g_uf[p];
        if (gp != p) g_uf[x] = gp;   // path halving (monotone; benign races)
        x = p;
    }
    return x;
}

__global__ void k_phase1(int M, int nc) {
    int t = threadIdx.x;
    for (int c = 0; c < nc; c++) {
        int base = c * CHUNK;
        int n = min(CHUNK, M - base);
        // (a) snapshot labels of this chunk's endpoints (partition BEFORE this chunk)
        for (int e = t; e < n; e += blockDim.x) {
            unsigned long long cur = g_esort[base + e];
            unsigned int u = (unsigned int)cur & 0xFFFFu;
            unsigned int v = ((unsigned int)cur >> 16) & 0xFFFFu;
            g_lab[2 * (base + e)]     = (unsigned short)gfind(u);
            g_lab[2 * (base + e) + 1] = (unsigned short)gfind(v);
        }
        __syncthreads();
        // (b) hook this chunk's edges (ECL-CC style: CAS only on roots)
        for (int e = t; e < n; e += blockDim.x) {
            unsigned long long cur = g_esort[base + e];
            unsigned int u = (unsigned int)cur & 0xFFFFu;
            unsigned int v = ((unsigned int)cur >> 16) & 0xFFFFu;
            for (;;) {
                unsigned int a = gfind(u), b = gfind(v);
                if (a == b) break;
                unsigned int hi = a > b ? a : b;
                unsigned int lo = a ^ b ^ hi;
                if (atomicCAS(&g_uf[hi], hi, lo) == hi) break;
            }
        }
        __syncthreads();
    }
}

// ---------------- phase 2: independent serial replay per chunk ----------------
__device__ __forceinline__ unsigned int uf_find(volatile unsigned short* uf, unsigned int x) {
    unsigned int r = x, p;
    while ((p = uf[r]) != r) r = p;
    while ((p = uf[x]) != r) { uf[x] = (unsigned short)r; x = p; }
    return r;
}

__global__ void __launch_bounds__(1024) k_phase2(int M) {
    extern __shared__ unsigned short s_uf[];   // 65536 x u16 = 128KB, label-keyed
    int c = blockIdx.x;
    int base = c * CHUNK;
    int n = min(CHUNK, M - base);
    unsigned int* uf32 = (unsigned int*)s_uf;
    for (int i = threadIdx.x; i < L_ / 2; i += blockDim.x)
        uf32[i] = (2u * i) | ((2u * i + 1u) << 16);
    __syncthreads();
    if (threadIdx.x == 0) {
        unsigned int cnt = 0;
        for (int e = 0; e < n; e++) {
            unsigned int la = g_lab[2 * (base + e)];
            unsigned int lb = g_lab[2 * (base + e) + 1];
            unsigned int a = uf_find(s_uf, la);
            unsigned int b = uf_find(s_uf, lb);
            if (a == b) continue;                     // rejected
            unsigned int w = a < b ? a : b;
            unsigned int l = a ^ b ^ w;
            s_uf[l] = (unsigned short)w;              // union by min label
            g_recTmp[base + cnt] = (w << 16) | l;
            g_srcTmp[base + cnt] = (unsigned int)(base + e);
            cnt++;
        }
        g_acnt[c] = cnt;
    }
}

__global__ void k_ascan(int nc) {
    __shared__ unsigned int s[NCMAX];
    int t = threadIdx.x;
    unsigned int x = (t < nc) ? g_acnt[t] : 0u;
    s[t] = x;
    __syncthreads();
    for (int off = 1; off < NCMAX; off <<= 1) {
        unsigned int y = (t >= off) ? s[t - off] : 0u;
        __syncthreads();
        s[t] += y;
        __syncthreads();
    }
    if (t < nc) g_abase[t] = s[t] - x;   // exclusive
}

__global__ void k_ascatter(int nc) {
    int i = blockIdx.x * blockDim.x + threadIdx.x;
    int c = i / CHUNK, li = i % CHUNK;
    if (c >= nc || (unsigned int)li >= g_acnt[c]) return;
    unsigned int slot = g_abase[c] + (unsigned int)li;
    g_rec[slot] = g_recTmp[c * CHUNK + li];
    unsigned int e = g_srcTmp[c * CHUNK + li];
    g_alt[L_ + slot] = __uint_as_float((unsigned int)(g_esort[e] >> 32));
}

// ---------------- derive parents + children from merge records ----------------
__global__ void k_hist() {
    int k = blockIdx.x * blockDim.x + threadIdx.x;
    if (k >= MACC) return;
    unsigned int rec = g_rec[k];
    atomicAdd(&g_cnt[rec >> 16], 1u);
    atomicAdd(&g_cnt[rec & 0xFFFFu], 1u);
}

__global__ void k_offscan() {
    __shared__ unsigned int s[1024];
    __shared__ unsigned int s_run;
    int t = threadIdx.x;
    if (t == 0) s_run = 0u;
    __syncthreads();
    for (int c = 0; c < L_ / 1024; c++) {
        unsigned int x = g_cnt[c * 1024 + t];
        s[t] = x;
        __syncthreads();
        for (int off = 1; off < 1024; off <<= 1) {
            unsigned int y = (t >= off) ? s[t - off] : 0u;
            __syncthreads();
            s[t] += y;
            __syncthreads();
        }
        unsigned int run = s_run;
        g_offs[c * 1024 + t] = run + s[t] - x;
        g_cnt[c * 1024 + t] = 0u;
        unsigned int tot = s[1023];
        __syncthreads();
        if (t == 0) s_run = run + tot;
        __syncthreads();
    }
}

__global__ void k_scatter() {
    int k = blockIdx.x * blockDim.x + threadIdx.x;
    if (k >= MACC) return;
    unsigned int rec = g_rec[k];
    unsigned int w = rec >> 16, l = rec & 0xFFFFu;
    g_evt[g_offs[w] + atomicAdd(&g_cnt[w], 1u)] = (unsigned int)k;
    g_evt[g_offs[l] + atomicAdd(&g_cnt[l], 1u)] = (unsigned int)k;
}

__global__ void k_vlink() {
    int v = blockIdx.x * blockDim.x + threadIdx.x;
    if (v >= L_) return;
    unsigned int n = g_cnt[v], base = g_offs[v];
    if (n == 0) return;
    for (unsigned int i = 0; i + 1 < n; i++) {       // selection sort, avg n=2
        unsigned int mi = i, mv = g_evt[base + i];
        for (unsigned int j = i + 1; j < n; j++) {
            unsigned int x = g_evt[base + j];
            if (x < mv) { mv = x; mi = j; }
        }
        if (mi != i) { g_evt[base + mi] = g_evt[base + i]; g_evt[base + i] = mv; }
    }
    unsigned int prevnode = (unsigned int)v;
    for (unsigned int i = 0; i < n; i++) {
        unsigned int e = g_evt[base + i];
        unsigned int node = L_ + e;
        g_parent[prevnode] = node;
        if ((g_rec[e] >> 16) == (unsigned int)v) g_chw[e] = prevnode;
        else                                     g_chl[e] = prevnode;
        prevnode = node;
    }
}

// ---------------- Euler tour construction + list ranking ----------------
__global__ void k_euler() {
    int n = blockIdx.x * blockDim.x + threadIdx.x;
    if (n >= NN) return;
    if (n == 0) { g_nx[0][ESENT] = ESENT; g_dd[0][ESENT] = 0u; }
    g_dd[0][n]      = 1u;
    g_dd[0][NN + n] = 1u;
    if (n < L_) {
        g_nx[0][n] = NN + n;
    } else {
        int k = n - L_;
        unsigned int cw = g_chw[k], cl = g_chl[k];
        g_nx[0][n] = cw;
        g_nx[0][NN + cw] = cl;
        g_nx[0][NN + cl] = NN + n;
    }
    if (n == NN - 1) g_nx[0][NN + n] = ESENT;
}

__global__ void k_rank(int s) {
    int e = blockIdx.x * blockDim.x + threadIdx.x;
    if (e > ELEN) return;
    unsigned int nx = g_nx[s][e];
    g_dd[1 - s][e] = g_dd[s][e] + g_dd[s][nx];
    g_nx[1 - s][e] = g_nx[s][nx];
}

__global__ void k_pos(int fin) {
    int e = blockIdx.x * blockDim.x + threadIdx.x;
    if (e < ELEN) g_pos[e] = (unsigned int)ELEN - g_dd[fin][e];
}

// ---------------- Euler value planes: moments of altp(leaf) ----------------
__global__ void k_ezero() {
    int i = blockIdx.x * blockDim.x + threadIdx.x;
    if (i < 10 * EP) g_ev[i] = 0.0f;
}

__global__ void k_escatter() {
    int x = blockIdx.x * blockDim.x + threadIdx.x;
    if (x >= L_) return;
    unsigned int p = g_pos[x];
    float y = g_alt[g_parent[x]];
    float pw = 1.0f;
    #pragma unroll
    for (int i = 0; i < 10; i++) { g_ev[i * EP + p] = pw; pw *= y; }
}

// ---------------- 3-phase inclusive prefix scan over each plane ----------------
__global__ void k_scan1() {
    __shared__ float s[1024];
    int plane = blockIdx.y;
    int gi = blockIdx.x * 1024 + threadIdx.x;
    int t = threadIdx.x;
    float x = g_ev[plane * EP + gi];
    s[t] = x;
    __syncthreads();
    for (int off = 1; off < 1024; off <<= 1) {
        float y = (t >= off) ? s[t - off] : 0.0f;
        __syncthreads();
        s[t] += y;
        __syncthreads();
    }
    g_ev[plane * EP + gi] = s[t];
    if (t == 1023) g_part[plane * 256 + blockIdx.x] = s[1023];
}

__global__ void k_scan2() {
    __shared__ float s[256];
    int plane = blockIdx.y;
    int t = threadIdx.x;
    float x = g_part[plane * 256 + t];
    s[t] = x;
    __syncthreads();
    for (int off = 1; off < 256; off <<= 1) {
        float y = (t >= off) ? s[t - off] : 0.0f;
        __syncthreads();
        s[t] += y;
        __syncthreads();
    }
    g_part[plane * 256 + t] = s[t] - x;   // exclusive
}

__global__ void k_scan3() {
    int plane = blockIdx.y;
    int gi = blockIdx.x * 1024 + threadIdx.x;
    g_ev[plane * EP + gi] += g_part[plane * 256 + blockIdx.x];
}

// ---------------- sigmoid via degree-9 Taylor, binomial moment combine ----------------
__device__ __forceinline__ float sig_combine(float x, const float* A) {
    float xp[10];
    xp[0] = 1.0f;
    #pragma unroll
    for (int p = 1; p < 10; p++) xp[p] = xp[p - 1] * x;
    float B0 = A[0];
    float B1 = xp[1] * A[0] - A[1];
    float B3 = xp[3] * A[0] - 3.0f * xp[2] * A[1] + 3.0f * xp[1] * A[2] - A[3];
    float B5 = xp[5] * A[0] - 5.0f * xp[4] * A[1] + 10.0f * xp[3] * A[2]
             - 10.0f * xp[2] * A[3] + 5.0f * xp[1] * A[4] - A[5];
    float B7 = xp[7] * A[0] - 7.0f * xp[6] * A[1] + 21.0f * xp[5] * A[2]
             - 35.0f * xp[4] * A[3] + 35.0f * xp[3] * A[4] - 21.0f * xp[2] * A[5]
             + 7.0f * xp[1] * A[6] - A[7];
    float B9 = xp[9] * A[0] - 9.0f * xp[8] * A[1] + 36.0f * xp[7] * A[2]
             - 84.0f * xp[6] * A[3] + 126.0f * xp[5] * A[4] - 126.0f * xp[4] * A[5]
             + 84.0f * xp[3] * A[6] - 36.0f * xp[2] * A[7] + 9.0f * xp[1] * A[8] - A[9];
    return 0.5f * B0 + 0.25f * B1 - 0.0208333333f * B3 + 0.0020833333f * B5
         - 2.1081349e-4f * B7 + 2.1357107e-5f * B9;
}

// ---------------- subtree moments -> sizes + inside ----------------
__global__ void k_subtree() {
    int k = blockIdx.x * blockDim.x + threadIdx.x;
    if (k >= MACC) return;
    int a = L_ + k;
    unsigned int pd = g_pos[a], pu = g_pos[NN + a];
    float T[10];
    #pragma unroll
    for (int i = 0; i < 10; i++) T[i] = g_ev[i * EP + pu] - g_ev[i * EP + pd];
    g_sizes[a] = T[0];
    g_ins[a] = sig_combine(g_alt[a], T);
}

// ---------------- ancestor path-sum doubling for outside ----------------
__global__ void k_rinit() {
    int n = blockIdx.x * blockDim.x + threadIdx.x;
    if (n > NN) return;
    if (n == NN) {
        #pragma unroll
        for (int i = 0; i < 10; i++) g_R[0][n * 12 + i] = 0.0f;
        g_j[0][n] = NILN;
        return;
    }
    float sz = g_sizes[n];
    float x  = g_alt[n];
    unsigned int p = g_parent[n];
    bool isroot = (p == (unsigned int)n);
    float y = g_alt[p];
    float xp = 1.0f, yp = 1.0f;
    #pragma unroll
    for (int i = 0; i < 10; i++) {
        g_R[0][n * 12 + i] = sz * (xp - (isroot ? 0.0f : yp));
        xp *= x; yp *= y;
    }
    g_j[0][n] = isroot ? NILN : p;
}

__global__ void k_rdouble(int s) {
    int n = blockIdx.x * blockDim.x + threadIdx.x;
    if (n > NN) return;
    unsigned int j = g_j[s][n];
    #pragma unroll
    for (int i = 0; i < 10; i++)
        g_R[1 - s][n * 12 + i] = g_R[s][n * 12 + i] + g_R[s][j * 12 + i];
    g_j[1 - s][n] = g_j[s][j];
}

// ---------------- final: out = outside + (leaf ? 0.5 : inside) ----------------
__global__ void k_final(float* __restrict__ out, int fin) {
    int n = blockIdx.x * blockDim.x + threadIdx.x;
    if (n >= NN) return;
    float x  = g_alt[n];
    float sz = g_sizes[n];
    float A[10];
    float xp = 1.0f;
    #pragma unroll
    for (int i = 0; i < 10; i++) {
        A[i] = g_R[fin][n * 12 + i] - sz * xp;
        xp *= x;
    }
    float outside = sig_combine(x, A);
    out[n] = outside + (n < L_ ? 0.5f : g_ins[n]);
}

// ---------------- launch ----------------
extern "C" void kernel_launch(void* const* d_in, const int* in_sizes, int n_in,
                              void* d_out, int out_size) {
    const float* ew  = (const float*)d_in[0];
    const int*   src = (const int*)d_in[1];
    const int*   dst = (const int*)d_in[2];
    int M = in_sizes[0];   // 130560
    int nc = (M + CHUNK - 1) / CHUNK;   // 128

    k_init<<<NPAD / 256, 256>>>(ew, M);

    k_bitonic_local_init<<<NPAD / 2048, 1024>>>();
    for (int k = 4096; k <= NPAD; k <<= 1) {
        for (int j = k >> 1; j >= 2048; j >>= 1)
            k_bitonic_global<<<(NPAD / 2) / 256, 256>>>(j, k);
        k_bitonic_local_tail<<<NPAD / 2048, 1024>>>(k);
    }

    k_gather<<<NPAD / 256, 256>>>(src, dst, M);

    // tree build: boundary labels (serial chunks, parallel inside) + parallel chunk replays
    k_phase1<<<1, 1024>>>(M, nc);
    cudaFuncSetAttribute(k_phase2, cudaFuncAttributeMaxDynamicSharedMemorySize, L_ * 2);
    k_phase2<<<nc, 1024, L_ * 2>>>(M);
    k_ascan<<<1, NCMAX>>>(nc);
    k_ascatter<<<(nc * CHUNK + 255) / 256, 256>>>(nc);

    k_hist<<<(MACC + 255) / 256, 256>>>();
    k_offscan<<<1, 1024>>>();
    k_scatter<<<(MACC + 255) / 256, 256>>>();
    k_vlink<<<(L_ + 255) / 256, 256>>>();

    // Euler tour + list ranking (18 doubling rounds: 2^18 >= ELEN)
    k_euler<<<(NN + 255) / 256, 256>>>();
    int s = 0;
    for (int r = 0; r < 18; r++) {
        k_rank<<<(ELEN + 1 + 255) / 256, 256>>>(s);
        s = 1 - s;
    }
    k_pos<<<(ELEN + 255) / 256, 256>>>(s);

    // subtree moments via prefix scans over Euler order
    k_ezero<<<(10 * EP) / 256, 256>>>();
    k_escatter<<<(L_ + 255) / 256, 256>>>();
    {
        dim3 g1(256, 10); k_scan1<<<g1, 1024>>>();
        dim3 g2(1, 10);   k_scan2<<<g2, 256>>>();
        dim3 g3(256, 10); k_scan3<<<g3, 1024>>>();
    }
    k_subtree<<<(MACC + 255) / 256, 256>>>();

    // ancestor path sums via pointer doubling (17 rounds: 2^17 >= max depth)
    k_rinit<<<(NN + 1 + 255) / 256, 256>>>();
    int t = 0;
    for (int r = 0; r < 17; r++) {
        k_rdouble<<<(NN + 1 + 255) / 256, 256>>>(t);
        t = 1 - t;
    }

    k_final<<<(NN + 255) / 256, 256>>>((float*)d_out, t);
}

// round 8
// speedup vs baseline: 42.7066x; 10.7872x over previous
#include <cuda_runtime.h>
#include <cstdint>

// Problem constants (256x256 grid, 4-adjacency)
#define L_    65536      // leaves
#define NN    131071     // 2L-1 nodes
#define NPAD  262144     // 2^18 >= 130560 edges
#define MACC  (L_ - 1)   // accepted merges = 65535
#define FULLM 0xFFFFFFFFu
#define ELEN  (2 * NN)   // Euler elements = 262142
#define ESENT ELEN       // sentinel element
#define EP    262144     // Euler plane stride (pow2 >= ELEN)
#define NILN  NN         // sentinel node for jump pointers
#define CHUNK 1024       // edges per rank chunk
#define NCMAX 256
#define EVN   131072     // 2^17 >= 2*MACC event keys

// ---------------- device scratch ----------------
__device__ unsigned long long g_keys[NPAD];
__device__ unsigned long long g_esort[NPAD];
__device__ unsigned int   g_uf[L_];           // phase-1 global UF (root = component min)
__device__ unsigned short g_lab[2 * NPAD];    // endpoint labels at chunk start
__device__ unsigned int   g_recTmp[NPAD];     // per-chunk records
__device__ unsigned int   g_srcTmp[NPAD];     // per-chunk source edge index
__device__ unsigned int   g_acnt[NCMAX];      // accepted per chunk
__device__ unsigned int   g_abase[NCMAX];     // exclusive scan of acnt
__device__ unsigned int g_rec[MACC];          // accepted i -> (win_min<<16)|lose_min
__device__ unsigned int g_ev2[EVN];           // event keys (v<<16)|k, then sorted
__device__ unsigned int g_parent[NN];
__device__ float        g_alt[NN];
__device__ float        g_sizes[NN];
__device__ unsigned int g_chw[MACC];          // child node on win-min side
__device__ unsigned int g_chl[MACC];          // child node on lose-min side
__device__ unsigned int g_nx[2][ELEN + 1];    // Euler next ptr (ping-pong)
__device__ unsigned int g_dd[2][ELEN + 1];    // distance-to-end (ping-pong)
__device__ unsigned int g_pos[ELEN];          // Euler position
__device__ float        g_ev[10 * EP];        // Euler value planes (moments 0..9)
__device__ float        g_part[10 * 256];     // scan block partials
__device__ float        g_ins[NN];            // inside(a) for internal nodes
__device__ float        g_R[2][(NN + 1) * 12]; // path-sum vectors (10 used, pad 12)
__device__ unsigned int g_j[2][NN + 1];       // jump pointers

// ---------------- init ----------------
__global__ void k_init(const float* __restrict__ ew, int M) {
    int i = blockIdx.x * blockDim.x + threadIdx.x;
    if (i < NPAD) {
        if (i < M) {
            unsigned int wb = __float_as_uint(ew[i]);  // weights in [0,1): bits monotone
            g_keys[i] = ((unsigned long long)wb << 32) | (unsigned int)i;
        } else {
            g_keys[i] = ~0ull;
        }
    }
    if (i < L_) g_uf[i] = (unsigned int)i;
    if (i < NN) { g_parent[i] = i; g_alt[i] = 0.0f; g_sizes[i] = (i < L_) ? 1.0f : 0.0f; }
}

// ---------------- bitonic sort, 64-bit keys ----------------
__global__ void k_bitonic_local_init() {
    __shared__ unsigned long long s[2048];
    int base = blockIdx.x * 2048;
    int t = threadIdx.x;
    s[t]        = g_keys[base + t];
    s[t + 1024] = g_keys[base + t + 1024];
    __syncthreads();
    for (int k = 2; k <= 2048; k <<= 1) {
        for (int j = k >> 1; j > 0; j >>= 1) {
            int pos = ((t & ~(j - 1)) << 1) | (t & (j - 1));
            int gi  = base + pos;
            bool asc = ((gi & k) == 0);
            unsigned long long x = s[pos], y = s[pos + j];
            if ((x > y) == asc) { s[pos] = y; s[pos + j] = x; }
            __syncthreads();
        }
    }
    g_keys[base + t]        = s[t];
    g_keys[base + t + 1024] = s[t + 1024];
}

__global__ void k_bitonic_global(int j, int k) {
    int t = blockIdx.x * blockDim.x + threadIdx.x;
    int i = ((t & ~(j - 1)) << 1) | (t & (j - 1));
    int l = i + j;
    bool asc = ((i & k) == 0);
    unsigned long long x = g_keys[i], y = g_keys[l];
    if ((x > y) == asc) { g_keys[i] = y; g_keys[l] = x; }
}

__global__ void k_bitonic_local_tail(int k) {
    __shared__ unsigned long long s[2048];
    int base = blockIdx.x * 2048;
    int t = threadIdx.x;
    s[t]        = g_keys[base + t];
    s[t + 1024] = g_keys[base + t + 1024];
    __syncthreads();
    bool asc = ((base & k) == 0);
    for (int j = 1024; j > 0; j >>= 1) {
        int pos = ((t & ~(j - 1)) << 1) | (t & (j - 1));
        unsigned long long x = s[pos], y = s[pos + j];
        if ((x > y) == asc) { s[pos] = y; s[pos + j] = x; }
        __syncthreads();
    }
    g_keys[base + t]        = s[t];
    g_keys[base + t + 1024] = s[t + 1024];
}

// ---------------- bitonic sort, 32-bit keys (event array) ----------------
__global__ void k_bsort32_local_init() {
    __shared__ unsigned int s[2048];
    int base = blockIdx.x * 2048;
    int t = threadIdx.x;
    s[t]        = g_ev2[base + t];
    s[t + 1024] = g_ev2[base + t + 1024];
    __syncthreads();
    for (int k = 2; k <= 2048; k <<= 1) {
        for (int j = k >> 1; j > 0; j >>= 1) {
            int pos = ((t & ~(j - 1)) << 1) | (t & (j - 1));
            int gi  = base + pos;
            bool asc = ((gi & k) == 0);
            unsigned int x = s[pos], y = s[pos + j];
            if ((x > y) == asc) { s[pos] = y; s[pos + j] = x; }
            __syncthreads();
        }
    }
    g_ev2[base + t]        = s[t];
    g_ev2[base + t + 1024] = s[t + 1024];
}

__global__ void k_bsort32_global(int j, int k) {
    int t = blockIdx.x * blockDim.x + threadIdx.x;
    int i = ((t & ~(j - 1)) << 1) | (t & (j - 1));
    int l = i + j;
    bool asc = ((i & k) == 0);
    unsigned int x = g_ev2[i], y = g_ev2[l];
    if ((x > y) == asc) { g_ev2[i] = y; g_ev2[l] = x; }
}

__global__ void k_bsort32_local_tail(int k) {
    __shared__ unsigned int s[2048];
    int base = blockIdx.x * 2048;
    int t = threadIdx.x;
    s[t]        = g_ev2[base + t];
    s[t + 1024] = g_ev2[base + t + 1024];
    __syncthreads();
    bool asc = ((base & k) == 0);
    for (int j = 1024; j > 0; j >>= 1) {
        int pos = ((t & ~(j - 1)) << 1) | (t & (j - 1));
        unsigned int x = s[pos], y = s[pos + j];
        if ((x > y) == asc) { s[pos] = y; s[pos + j] = x; }
        __syncthreads();
    }
    g_ev2[base + t]        = s[t];
    g_ev2[base + t + 1024] = s[t + 1024];
}

// ---------------- gather sorted edge endpoints ----------------
__global__ void k_gather(const int* __restrict__ src, const int* __restrict__ dst, int M) {
    int e = blockIdx.x * blockDim.x + threadIdx.x;
    if (e >= NPAD) return;
    if (e < M) {
        unsigned long long key = g_keys[e];
        unsigned int idx = (unsigned int)(key & 0xFFFFFFFFull);
        unsigned int wb  = (unsigned int)(key >> 32);
        unsigned int u = (unsigned int)src[idx];
        unsigned int v = (unsigned int)dst[idx];
        g_esort[e] = ((unsigned long long)wb << 32) | (v << 16) | u;
    } else {
        g_esort[e] = 0ull;
    }
}

// ---------------- phase 1: chunk-boundary labels via parallel UF (single block) --------
__device__ __forceinline__ unsigned int gfind(unsigned int x) {
    unsigned int p;
    while ((p = g_uf[x]) != x) {
        unsigned int gp = g_uf[p];
        if (gp != p) g_uf[x] = gp;   // path halving (monotone; benign races)
        x = p;
    }
    return x;
}

__global__ void k_phase1(int M, int nc) {
    int t = threadIdx.x;
    for (int c = 0; c < nc; c++) {
        int base = c * CHUNK;
        int n = min(CHUNK, M - base);
        for (int e = t; e < n; e += blockDim.x) {
            unsigned long long cur = g_esort[base + e];
            unsigned int u = (unsigned int)cur & 0xFFFFu;
            unsigned int v = ((unsigned int)cur >> 16) & 0xFFFFu;
            g_lab[2 * (base + e)]     = (unsigned short)gfind(u);
            g_lab[2 * (base + e) + 1] = (unsigned short)gfind(v);
        }
        __syncthreads();
        for (int e = t; e < n; e += blockDim.x) {
            unsigned long long cur = g_esort[base + e];
            unsigned int u = (unsigned int)cur & 0xFFFFu;
            unsigned int v = ((unsigned int)cur >> 16) & 0xFFFFu;
            for (;;) {
                unsigned int a = gfind(u), b = gfind(v);
                if (a == b) break;
                unsigned int hi = a > b ? a : b;
                unsigned int lo = a ^ b ^ hi;
                if (atomicCAS(&g_uf[hi], hi, lo) == hi) break;
            }
        }
        __syncthreads();
    }
}

// ---------------- phase 2: independent serial replay per chunk ----------------
__device__ __forceinline__ unsigned int uf_find(volatile unsigned short* uf, unsigned int x) {
    unsigned int r = x, p;
    while ((p = uf[r]) != r) r = p;
    while ((p = uf[x]) != r) { uf[x] = (unsigned short)r; x = p; }
    return r;
}

__global__ void __launch_bounds__(1024) k_phase2(int M) {
    extern __shared__ unsigned short s_uf[];   // 65536 x u16 = 128KB, label-keyed
    int c = blockIdx.x;
    int base = c * CHUNK;
    int n = min(CHUNK, M - base);
    unsigned int* uf32 = (unsigned int*)s_uf;
    for (int i = threadIdx.x; i < L_ / 2; i += blockDim.x)
        uf32[i] = (2u * i) | ((2u * i + 1u) << 16);
    __syncthreads();
    if (threadIdx.x == 0) {
        unsigned int cnt = 0;
        for (int e = 0; e < n; e++) {
            unsigned int la = g_lab[2 * (base + e)];
            unsigned int lb = g_lab[2 * (base + e) + 1];
            unsigned int a = uf_find(s_uf, la);
            unsigned int b = uf_find(s_uf, lb);
            if (a == b) continue;
            unsigned int w = a < b ? a : b;
            unsigned int l = a ^ b ^ w;
            s_uf[l] = (unsigned short)w;
            g_recTmp[base + cnt] = (w << 16) | l;
            g_srcTmp[base + cnt] = (unsigned int)(base + e);
            cnt++;
        }
        g_acnt[c] = cnt;
    }
}

__global__ void k_ascan(int nc) {
    __shared__ unsigned int s[NCMAX];
    int t = threadIdx.x;
    unsigned int x = (t < nc) ? g_acnt[t] : 0u;
    s[t] = x;
    __syncthreads();
    for (int off = 1; off < NCMAX; off <<= 1) {
        unsigned int y = (t >= off) ? s[t - off] : 0u;
        __syncthreads();
        s[t] += y;
        __syncthreads();
    }
    if (t < nc) g_abase[t] = s[t] - x;   // exclusive
}

__global__ void k_ascatter(int nc) {
    int i = blockIdx.x * blockDim.x + threadIdx.x;
    int c = i / CHUNK, li = i % CHUNK;
    if (c >= nc || (unsigned int)li >= g_acnt[c]) return;
    unsigned int slot = g_abase[c] + (unsigned int)li;
    g_rec[slot] = g_recTmp[c * CHUNK + li];
    unsigned int e = g_srcTmp[c * CHUNK + li];
    g_alt[L_ + slot] = __uint_as_float((unsigned int)(g_esort[e] >> 32));
}

// ---------------- event keys: (vertex<<16)|rank, sorted => per-vertex rank-ordered ------
__global__ void k_evinit() {
    int i = blockIdx.x * blockDim.x + threadIdx.x;
    if (i >= EVN) return;
    if (i < 2 * MACC) {
        unsigned int k = (unsigned int)(i >> 1);
        unsigned int rec = g_rec[k];
        unsigned int v = (i & 1) ? (rec & 0xFFFFu) : (rec >> 16);
        g_ev2[i] = (v << 16) | k;      // real keys <= 0xFFFE FFFE < pad
    } else {
        g_ev2[i] = FULLM;
    }
}

// parallel chain links from sorted events: each sorted index = one adjacency
__global__ void k_vlink2() {
    int i = blockIdx.x * blockDim.x + threadIdx.x;
    if (i >= 2 * MACC) return;
    unsigned int key = g_ev2[i];
    unsigned int v = key >> 16, k = key & 0xFFFFu;
    unsigned int prevnode;
    if (i == 0 || (g_ev2[i - 1] >> 16) != v)
        prevnode = v;                          // segment start: chain begins at leaf v
    else
        prevnode = L_ + (g_ev2[i - 1] & 0xFFFFu);
    g_parent[prevnode] = L_ + k;
    if ((g_rec[k] >> 16) == v) g_chw[k] = prevnode;
    else                       g_chl[k] = prevnode;
}

// ---------------- Euler tour construction + list ranking ----------------
__global__ void k_euler() {
    int n = blockIdx.x * blockDim.x + threadIdx.x;
    if (n >= NN) return;
    if (n == 0) { g_nx[0][ESENT] = ESENT; g_dd[0][ESENT] = 0u; }
    g_dd[0][n]      = 1u;
    g_dd[0][NN + n] = 1u;
    if (n < L_) {
        g_nx[0][n] = NN + n;
    } else {
        int k = n - L_;
        unsigned int cw = g_chw[k], cl = g_chl[k];
        g_nx[0][n] = cw;
        g_nx[0][NN + cw] = cl;
        g_nx[0][NN + cl] = NN + n;
    }
    if (n == NN - 1) g_nx[0][NN + n] = ESENT;
}

__global__ void k_rank(int s) {
    int e = blockIdx.x * blockDim.x + threadIdx.x;
    if (e > ELEN) return;
    unsigned int nx = g_nx[s][e];
    g_dd[1 - s][e] = g_dd[s][e] + g_dd[s][nx];
    g_nx[1 - s][e] = g_nx[s][nx];
}

__global__ void k_pos(int fin) {
    int e = blockIdx.x * blockDim.x + threadIdx.x;
    if (e < ELEN) g_pos[e] = (unsigned int)ELEN - g_dd[fin][e];
}

// ---------------- Euler value planes: moments of altp(leaf) ----------------
__global__ void k_ezero() {
    int i = blockIdx.x * blockDim.x + threadIdx.x;
    if (i < 10 * EP) g_ev[i] = 0.0f;
}

__global__ void k_escatter() {
    int x = blockIdx.x * blockDim.x + threadIdx.x;
    if (x >= L_) return;
    unsigned int p = g_pos[x];
    float y = g_alt[g_parent[x]];
    float pw = 1.0f;
    #pragma unroll
    for (int i = 0; i < 10; i++) { g_ev[i * EP + p] = pw; pw *= y; }
}

// ---------------- 3-phase inclusive prefix scan over each plane ----------------
__global__ void k_scan1() {
    __shared__ float s[1024];
    int plane = blockIdx.y;
    int gi = blockIdx.x * 1024 + threadIdx.x;
    int t = threadIdx.x;
    float x = g_ev[plane * EP + gi];
    s[t] = x;
    __syncthreads();
    for (int off = 1; off < 1024; off <<= 1) {
        float y = (t >= off) ? s[t - off] : 0.0f;
        __syncthreads();
        s[t] += y;
        __syncthreads();
    }
    g_ev[plane * EP + gi] = s[t];
    if (t == 1023) g_part[plane * 256 + blockIdx.x] = s[1023];
}

__global__ void k_scan2() {
    __shared__ float s[256];
    int plane = blockIdx.y;
    int t = threadIdx.x;
    float x = g_part[plane * 256 + t];
    s[t] = x;
    __syncthreads();
    for (int off = 1; off < 256; off <<= 1) {
        float y = (t >= off) ? s[t - off] : 0.0f;
        __syncthreads();
        s[t] += y;
        __syncthreads();
    }
    g_part[plane * 256 + t] = s[t] - x;   // exclusive
}

__global__ void k_scan3() {
    int plane = blockIdx.y;
    int gi = blockIdx.x * 1024 + threadIdx.x;
    g_ev[plane * EP + gi] += g_part[plane * 256 + blockIdx.x];
}

// ---------------- sigmoid via degree-9 Taylor, binomial moment combine ----------------
__device__ __forceinline__ float sig_combine(float x, const float* A) {
    float xp[10];
    xp[0] = 1.0f;
    #pragma unroll
    for (int p = 1; p < 10; p++) xp[p] = xp[p - 1] * x;
    float B0 = A[0];
    float B1 = xp[1] * A[0] - A[1];
    float B3 = xp[3] * A[0] - 3.0f * xp[2] * A[1] + 3.0f * xp[1] * A[2] - A[3];
    float B5 = xp[5] * A[0] - 5.0f * xp[4] * A[1] + 10.0f * xp[3] * A[2]
             - 10.0f * xp[2] * A[3] + 5.0f * xp[1] * A[4] - A[5];
    float B7 = xp[7] * A[0] - 7.0f * xp[6] * A[1] + 21.0f * xp[5] * A[2]
             - 35.0f * xp[4] * A[3] + 35.0f * xp[3] * A[4] - 21.0f * xp[2] * A[5]
             + 7.0f * xp[1] * A[6] - A[7];
    float B9 = xp[9] * A[0] - 9.0f * xp[8] * A[1] + 36.0f * xp[7] * A[2]
             - 84.0f * xp[6] * A[3] + 126.0f * xp[5] * A[4] - 126.0f * xp[4] * A[5]
             + 84.0f * xp[3] * A[6] - 36.0f * xp[2] * A[7] + 9.0f * xp[1] * A[8] - A[9];
    return 0.5f * B0 + 0.25f * B1 - 0.0208333333f * B3 + 0.0020833333f * B5
         - 2.1081349e-4f * B7 + 2.1357107e-5f * B9;
}

// ---------------- subtree moments -> sizes + inside ----------------
__global__ void k_subtree() {
    int k = blockIdx.x * blockDim.x + threadIdx.x;
    if (k >= MACC) return;
    int a = L_ + k;
    unsigned int pd = g_pos[a], pu = g_pos[NN + a];
    float T[10];
    #pragma unroll
    for (int i = 0; i < 10; i++) T[i] = g_ev[i * EP + pu] - g_ev[i * EP + pd];
    g_sizes[a] = T[0];
    g_ins[a] = sig_combine(g_alt[a], T);
}

// ---------------- ancestor path-sum doubling for outside ----------------
__global__ void k_rinit() {
    int n = blockIdx.x * blockDim.x + threadIdx.x;
    if (n > NN) return;
    if (n == NN) {
        #pragma unroll
        for (int i = 0; i < 10; i++) g_R[0][n * 12 + i] = 0.0f;
        g_j[0][n] = NILN;
        return;
    }
    float sz = g_sizes[n];
    float x  = g_alt[n];
    unsigned int p = g_parent[n];
    bool isroot = (p == (unsigned int)n);
    float y = g_alt[p];
    float xp = 1.0f, yp = 1.0f;
    #pragma unroll
    for (int i = 0; i < 10; i++) {
        g_R[0][n * 12 + i] = sz * (xp - (isroot ? 0.0f : yp));
        xp *= x; yp *= y;
    }
    g_j[0][n] = isroot ? NILN : p;
}

__global__ void k_rdouble(int s) {
    int n = blockIdx.x * blockDim.x + threadIdx.x;
    if (n > NN) return;
    unsigned int j = g_j[s][n];
    #pragma unroll
    for (int i = 0; i < 10; i++)
        g_R[1 - s][n * 12 + i] = g_R[s][n * 12 + i] + g_R[s][j * 12 + i];
    g_j[1 - s][n] = g_j[s][j];
}

// ---------------- final: out = outside + (leaf ? 0.5 : inside) ----------------
__global__ void k_final(float* __restrict__ out, int fin) {
    int n = blockIdx.x * blockDim.x + threadIdx.x;
    if (n >= NN) return;
    float x  = g_alt[n];
    float sz = g_sizes[n];
    float A[10];
    float xp = 1.0f;
    #pragma unroll
    for (int i = 0; i < 10; i++) {
        A[i] = g_R[fin][n * 12 + i] - sz * xp;
        xp *= x;
    }
    float outside = sig_combine(x, A);
    out[n] = outside + (n < L_ ? 0.5f : g_ins[n]);
}

// ---------------- launch ----------------
extern "C" void kernel_launch(void* const* d_in, const int* in_sizes, int n_in,
                              void* d_out, int out_size) {
    const float* ew  = (const float*)d_in[0];
    const int*   src = (const int*)d_in[1];
    const int*   dst = (const int*)d_in[2];
    int M = in_sizes[0];   // 130560
    int nc = (M + CHUNK - 1) / CHUNK;   // 128

    k_init<<<NPAD / 256, 256>>>(ew, M);

    k_bitonic_local_init<<<NPAD / 2048, 1024>>>();
    for (int k = 4096; k <= NPAD; k <<= 1) {
        for (int j = k >> 1; j >= 2048; j >>= 1)
            k_bitonic_global<<<(NPAD / 2) / 256, 256>>>(j, k);
        k_bitonic_local_tail<<<NPAD / 2048, 1024>>>(k);
    }

    k_gather<<<NPAD / 256, 256>>>(src, dst, M);

    k_phase1<<<1, 1024>>>(M, nc);
    cudaFuncSetAttribute(k_phase2, cudaFuncAttributeMaxDynamicSharedMemorySize, L_ * 2);
    k_phase2<<<nc, 1024, L_ * 2>>>(M);
    k_ascan<<<1, NCMAX>>>(nc);
    k_ascatter<<<(nc * CHUNK + 255) / 256, 256>>>(nc);

    // event sort (u32) + parallel chain links
    k_evinit<<<EVN / 256, 256>>>();
    k_bsort32_local_init<<<EVN / 2048, 1024>>>();
    for (int k = 4096; k <= EVN; k <<= 1) {
        for (int j = k >> 1; j >= 2048; j >>= 1)
            k_bsort32_global<<<(EVN / 2) / 256, 256>>>(j, k);
        k_bsort32_local_tail<<<EVN / 2048, 1024>>>(k);
    }
    k_vlink2<<<(2 * MACC + 255) / 256, 256>>>();

    // Euler tour + list ranking (18 doubling rounds: 2^18 >= ELEN)
    k_euler<<<(NN + 255) / 256, 256>>>();
    int s = 0;
    for (int r = 0; r < 18; r++) {
        k_rank<<<(ELEN + 1 + 255) / 256, 256>>>(s);
        s = 1 - s;
    }
    k_pos<<<(ELEN + 255) / 256, 256>>>(s);

    // subtree moments via prefix scans over Euler order
    k_ezero<<<(10 * EP) / 256, 256>>>();
    k_escatter<<<(L_ + 255) / 256, 256>>>();
    {
        dim3 g1(256, 10); k_scan1<<<g1, 1024>>>();
        dim3 g2(1, 10);   k_scan2<<<g2, 256>>>();
        dim3 g3(256, 10); k_scan3<<<g3, 1024>>>();
    }
    k_subtree<<<(MACC + 255) / 256, 256>>>();

    // ancestor path sums via pointer doubling (17 rounds: 2^17 >= max depth)
    k_rinit<<<(NN + 1 + 255) / 256, 256>>>();
    int t = 0;
    for (int r = 0; r < 17; r++) {
        k_rdouble<<<(NN + 1 + 255) / 256, 256>>>(t);
        t = 1 - t;
    }

    k_final<<<(NN + 255) / 256, 256>>>((float*)d_out, t);
}

// round 9
// speedup vs baseline: 72.1684x; 1.6899x over previous
#include <cuda_runtime.h>
#include <cstdint>

// Problem constants (256x256 grid, 4-adjacency)
#define L_    65536      // leaves
#define NN    131071     // 2L-1 nodes
#define NPAD  262144     // 2^18 >= 130560 edges
#define MACC  (L_ - 1)   // accepted merges = 65535
#define FULLM 0xFFFFFFFFu
#define ELEN  (2 * NN)   // Euler elements = 262142
#define ESENT ELEN       // sentinel element
#define EP    262144     // Euler plane stride (pow2 >= ELEN)
#define CHUNK 1024       // edges per rank chunk
#define NCMAX 256
#define EVN   131072     // 2^17 >= 2*MACC event keys
#define NB    8192       // sort buckets
#define BCAP  256        // bucket capacity

// ---------------- device scratch ----------------
__device__ unsigned long long g_keys2[NPAD];  // bucket-scattered (wbits<<32)|idx
__device__ unsigned int   g_bcnt[NB];
__device__ unsigned int   g_boffs[NB];
__device__ unsigned long long g_esort[NPAD];  // (wbits<<32)|(v<<16)|u in rank order
__device__ unsigned int   g_lab[NPAD];        // endpoint labels at chunk start (a|b<<16)
__device__ unsigned int   g_recTmp[NPAD];     // per-chunk records
__device__ unsigned int   g_srcTmp[NPAD];     // per-chunk source edge index
__device__ unsigned int   g_acnt[NCMAX];
__device__ unsigned int   g_abase[NCMAX];
__device__ unsigned int g_rec[MACC];          // accepted i -> (win_min<<16)|lose_min
__device__ unsigned int g_ev2[EVN];           // event keys (v<<16)|k, then sorted
__device__ unsigned int g_parent[NN];
__device__ float        g_alt[NN];
__device__ float        g_sizes[NN];
__device__ unsigned int g_chw[MACC];          // child node on win-min side
__device__ unsigned int g_chl[MACC];          // child node on lose-min side
__device__ unsigned int g_nx[2][ELEN + 1];    // Euler next ptr (ping-pong)
__device__ unsigned int g_dd[2][ELEN + 1];    // distance-to-end (ping-pong)
__device__ unsigned int g_pos[ELEN];          // Euler position
__device__ float        g_ev[20 * EP];        // planes 0..9 leaf moments, 10..19 path sums
__device__ float        g_part[20 * 256];     // scan block partials
__device__ float        g_ins[NN];            // inside(a) for internal nodes

// ---------------- init (fused zeroing) ----------------
__global__ void k_init(int M) {
    int i = blockIdx.x * blockDim.x + threadIdx.x;   // 262144 threads
    if (i < NN) { g_parent[i] = i; g_alt[i] = 0.0f; g_sizes[i] = (i < L_) ? 1.0f : 0.0f; }
    if (i < NB) g_bcnt[i] = 0u;
    if (i >= 2 * MACC && i < EVN) g_ev2[i] = FULLM;
    #pragma unroll
    for (int p = 0; p < 20; p++) g_ev[p * EP + i] = 0.0f;
}

// ---------------- bucket sort of (weight, idx) keys ----------------
__global__ void k_bhist(const float* __restrict__ ew, int M) {
    int e = blockIdx.x * blockDim.x + threadIdx.x;
    if (e >= M) return;
    unsigned int b = min((unsigned int)(ew[e] * (float)NB), (unsigned int)(NB - 1));
    atomicAdd(&g_bcnt[b], 1u);
}

__global__ void k_bscan() {
    __shared__ unsigned int s[1024];
    __shared__ unsigned int s_run;
    int t = threadIdx.x;
    if (t == 0) s_run = 0u;
    __syncthreads();
    for (int c = 0; c < NB / 1024; c++) {
        unsigned int x = g_bcnt[c * 1024 + t];
        s[t] = x;
        __syncthreads();
        for (int off = 1; off < 1024; off <<= 1) {
            unsigned int y = (t >= off) ? s[t - off] : 0u;
            __syncthreads();
            s[t] += y;
            __syncthreads();
        }
        unsigned int run = s_run;
        g_boffs[c * 1024 + t] = run + s[t] - x;   // exclusive
        g_bcnt[c * 1024 + t] = 0u;                // reset as scatter cursor
        unsigned int tot = s[1023];
        __syncthreads();
        if (t == 0) s_run = run + tot;
        __syncthreads();
    }
}

__global__ void k_bscatter(const float* __restrict__ ew, int M) {
    int e = blockIdx.x * blockDim.x + threadIdx.x;
    if (e >= M) return;
    float w = ew[e];
    unsigned int b = min((unsigned int)(w * (float)NB), (unsigned int)(NB - 1));
    unsigned int slot = g_boffs[b] + atomicAdd(&g_bcnt[b], 1u);
    g_keys2[slot] = ((unsigned long long)__float_as_uint(w) << 32) | (unsigned int)e;
}

// full in-bucket sort of unique keys restores exact stable global order
__global__ void k_bsort(const int* __restrict__ src, const int* __restrict__ dst) {
    __shared__ unsigned long long s[BCAP];
    int b = blockIdx.x;
    int t = threadIdx.x;          // 128 threads
    unsigned int cnt  = min(g_bcnt[b], (unsigned int)BCAP);
    unsigned int offs = g_boffs[b];
    for (int i = t; i < BCAP; i += 128)
        s[i] = (i < (int)cnt) ? g_keys2[offs + i] : ~0ull;
    __syncthreads();
    for (int k = 2; k <= BCAP; k <<= 1) {
        for (int j = k >> 1; j > 0; j >>= 1) {
            int pos = ((t & ~(j - 1)) << 1) | (t & (j - 1));
            bool asc = ((pos & k) == 0);
            unsigned long long x = s[pos], y = s[pos + j];
            if ((x > y) == asc) { s[pos] = y; s[pos + j] = x; }
            __syncthreads();
        }
    }
    for (int i = t; i < (int)cnt; i += 128) {
        unsigned long long key = s[i];
        unsigned int idx = (unsigned int)(key & 0xFFFFFFFFull);
        unsigned int wb  = (unsigned int)(key >> 32);
        unsigned int u = (unsigned int)src[idx];
        unsigned int v = (unsigned int)dst[idx];
        g_esort[offs + i] = ((unsigned long long)wb << 32) | (v << 16) | u;
    }
}

// ---------------- phase 1: chunk-boundary labels, UF in shared memory ----------------
__device__ __forceinline__ unsigned int sfind(volatile unsigned short* uf, unsigned int x) {
    unsigned int p;
    while ((p = uf[x]) != x) {
        unsigned int gp = uf[p];
        if (gp != p) uf[x] = (unsigned short)gp;   // path halving (benign races)
        x = p;
    }
    return x;
}

__global__ void __launch_bounds__(1024) k_phase1(int M, int nc) {
    extern __shared__ unsigned short s_uf[];   // 65536 x u16 = 128KB
    int t = threadIdx.x;
    unsigned int* uf32 = (unsigned int*)s_uf;
    for (int i = t; i < L_ / 2; i += 1024)
        uf32[i] = (2u * i) | ((2u * i + 1u) << 16);
    __syncthreads();
    for (int c = 0; c < nc; c++) {
        int base = c * CHUNK;
        int n = min(CHUNK, M - base);
        for (int e = t; e < n; e += 1024) {
            unsigned long long cur = g_esort[base + e];
            unsigned int u = (unsigned int)cur & 0xFFFFu;
            unsigned int v = ((unsigned int)cur >> 16) & 0xFFFFu;
            unsigned int a = sfind(s_uf, u);
            unsigned int b = sfind(s_uf, v);
            g_lab[base + e] = a | (b << 16);
        }
        __syncthreads();
        for (int e = t; e < n; e += 1024) {
            unsigned long long cur = g_esort[base + e];
            unsigned int u = (unsigned int)cur & 0xFFFFu;
            unsigned int v = ((unsigned int)cur >> 16) & 0xFFFFu;
            for (;;) {
                unsigned int a = sfind(s_uf, u), b = sfind(s_uf, v);
                if (a == b) break;
                unsigned int hi = a > b ? a : b;
                unsigned int lo = a ^ b ^ hi;
                if (atomicCAS((unsigned short*)&s_uf[hi], (unsigned short)hi,
                              (unsigned short)lo) == (unsigned short)hi) break;
            }
        }
        __syncthreads();
    }
}

// ---------------- phase 2: independent serial replay per chunk ----------------
__device__ __forceinline__ unsigned int uf_find(volatile unsigned short* uf, unsigned int x) {
    unsigned int r = x, p;
    while ((p = uf[r]) != r) r = p;
    while ((p = uf[x]) != r) { uf[x] = (unsigned short)r; x = p; }
    return r;
}

__global__ void __launch_bounds__(1024) k_phase2(int M) {
    extern __shared__ unsigned short s_uf[];
    int c = blockIdx.x;
    int base = c * CHUNK;
    int n = min(CHUNK, M - base);
    unsigned int* uf32 = (unsigned int*)s_uf;
    for (int i = threadIdx.x; i < L_ / 2; i += blockDim.x)
        uf32[i] = (2u * i) | ((2u * i + 1u) << 16);
    __syncthreads();
    if (threadIdx.x == 0) {
        unsigned int cnt = 0;
        for (int e = 0; e < n; e++) {
            unsigned int lab = g_lab[base + e];
            unsigned int a = uf_find(s_uf, lab & 0xFFFFu);
            unsigned int b = uf_find(s_uf, lab >> 16);
            if (a == b) continue;
            unsigned int w = a < b ? a : b;
            unsigned int l = a ^ b ^ w;
            s_uf[l] = (unsigned short)w;
            g_recTmp[base + cnt] = (w << 16) | l;
            g_srcTmp[base + cnt] = (unsigned int)(base + e);
            cnt++;
        }
        g_acnt[c] = cnt;
    }
}

__global__ void k_ascan(int nc) {
    __shared__ unsigned int s[NCMAX];
    int t = threadIdx.x;
    unsigned int x = (t < nc) ? g_acnt[t] : 0u;
    s[t] = x;
    __syncthreads();
    for (int off = 1; off < NCMAX; off <<= 1) {
        unsigned int y = (t >= off) ? s[t - off] : 0u;
        __syncthreads();
        s[t] += y;
        __syncthreads();
    }
    if (t < nc) g_abase[t] = s[t] - x;   // exclusive
}

__global__ void k_ascatter(int nc) {
    int i = blockIdx.x * blockDim.x + threadIdx.x;
    int c = i / CHUNK, li = i % CHUNK;
    if (c >= nc || (unsigned int)li >= g_acnt[c]) return;
    unsigned int slot = g_abase[c] + (unsigned int)li;
    unsigned int rec = g_recTmp[c * CHUNK + li];
    g_rec[slot] = rec;
    unsigned int e = g_srcTmp[c * CHUNK + li];
    g_alt[L_ + slot] = __uint_as_float((unsigned int)(g_esort[e] >> 32));
    g_ev2[2 * slot]     = ((rec >> 16) << 16) | slot;       // win event
    g_ev2[2 * slot + 1] = ((rec & 0xFFFFu) << 16) | slot;   // lose event
}

// ---------------- bitonic sort, 32-bit event keys ----------------
__global__ void k_bsort32_local_init() {
    __shared__ unsigned int s[2048];
    int base = blockIdx.x * 2048;
    int t = threadIdx.x;
    s[t]        = g_ev2[base + t];
    s[t + 1024] = g_ev2[base + t + 1024];
    __syncthreads();
    for (int k = 2; k <= 2048; k <<= 1) {
        for (int j = k >> 1; j > 0; j >>= 1) {
            int pos = ((t & ~(j - 1)) << 1) | (t & (j - 1));
            int gi  = base + pos;
            bool asc = ((gi & k) == 0);
            unsigned int x = s[pos], y = s[pos + j];
            if ((x > y) == asc) { s[pos] = y; s[pos + j] = x; }
            __syncthreads();
        }
    }
    g_ev2[base + t]        = s[t];
    g_ev2[base + t + 1024] = s[t + 1024];
}

__global__ void k_bsort32_global(int j, int k) {
    int t = blockIdx.x * blockDim.x + threadIdx.x;
    int i = ((t & ~(j - 1)) << 1) | (t & (j - 1));
    int l = i + j;
    bool asc = ((i & k) == 0);
    unsigned int x = g_ev2[i], y = g_ev2[l];
    if ((x > y) == asc) { g_ev2[i] = y; g_ev2[l] = x; }
}

__global__ void k_bsort32_local_tail(int k) {
    __shared__ unsigned int s[2048];
    int base = blockIdx.x * 2048;
    int t = threadIdx.x;
    s[t]        = g_ev2[base + t];
    s[t + 1024] = g_ev2[base + t + 1024];
    __syncthreads();
    bool asc = ((base & k) == 0);
    for (int j = 1024; j > 0; j >>= 1) {
        int pos = ((t & ~(j - 1)) << 1) | (t & (j - 1));
        unsigned int x = s[pos], y = s[pos + j];
        if ((x > y) == asc) { s[pos] = y; s[pos + j] = x; }
        __syncthreads();
    }
    g_ev2[base + t]        = s[t];
    g_ev2[base + t + 1024] = s[t + 1024];
}

// parallel chain links from sorted events
__global__ void k_vlink2() {
    int i = blockIdx.x * blockDim.x + threadIdx.x;
    if (i >= 2 * MACC) return;
    unsigned int key = g_ev2[i];
    unsigned int v = key >> 16, k = key & 0xFFFFu;
    unsigned int prevnode;
    if (i == 0 || (g_ev2[i - 1] >> 16) != v)
        prevnode = v;
    else
        prevnode = L_ + (g_ev2[i - 1] & 0xFFFFu);
    g_parent[prevnode] = L_ + k;
    if ((g_rec[k] >> 16) == v) g_chw[k] = prevnode;
    else                       g_chl[k] = prevnode;
}

// ---------------- Euler tour + list ranking ----------------
__global__ void k_euler() {
    int n = blockIdx.x * blockDim.x + threadIdx.x;
    if (n >= NN) return;
    if (n == 0) { g_nx[0][ESENT] = ESENT; g_dd[0][ESENT] = 0u; }
    g_dd[0][n]      = 1u;
    g_dd[0][NN + n] = 1u;
    if (n < L_) {
        g_nx[0][n] = NN + n;
    } else {
        int k = n - L_;
        unsigned int cw = g_chw[k], cl = g_chl[k];
        g_nx[0][n] = cw;
        g_nx[0][NN + cw] = cl;
        g_nx[0][NN + cl] = NN + n;
    }
    if (n == NN - 1) g_nx[0][NN + n] = ESENT;
}

__global__ void k_rank(int s) {
    int e = blockIdx.x * blockDim.x + threadIdx.x;
    if (e > ELEN) return;
    unsigned int nx = g_nx[s][e];
    g_dd[1 - s][e] = g_dd[s][e] + g_dd[s][nx];
    g_nx[1 - s][e] = g_nx[s][nx];
}

__global__ void k_pos(int fin) {
    int e = blockIdx.x * blockDim.x + threadIdx.x;
    if (e < ELEN) g_pos[e] = (unsigned int)ELEN - g_dd[fin][e];
}

// ---------------- Euler value planes ----------------
__global__ void k_escatter() {   // planes 0..9: leaf moments of alt(parent(leaf))
    int x = blockIdx.x * blockDim.x + threadIdx.x;
    if (x >= L_) return;
    unsigned int p = g_pos[x];
    float y = g_alt[g_parent[x]];
    float pw = 1.0f;
    #pragma unroll
    for (int i = 0; i < 10; i++) { g_ev[i * EP + p] = pw; pw *= y; }
}

// planes 10..19: +val at down(n), -val at up(n); prefix-incl at down(n) = ancestor sum
__global__ void k_pscatter() {
    int n = blockIdx.x * blockDim.x + threadIdx.x;
    if (n >= NN) return;
    float sz = g_sizes[n];
    float x  = g_alt[n];
    unsigned int p = g_parent[n];
    bool isroot = (p == (unsigned int)n);
    float y = g_alt[p];
    unsigned int pd = g_pos[n], pu = g_pos[NN + n];
    float xp = 1.0f, yp = 1.0f;
    #pragma unroll
    for (int i = 0; i < 10; i++) {
        float val = sz * (xp - (isroot ? 0.0f : yp));
        g_ev[(10 + i) * EP + pd] = val;
        g_ev[(10 + i) * EP + pu] = -val;
        xp *= x; yp *= y;
    }
}

// ---------------- 3-phase inclusive prefix scan (10 planes per round) ----------------
__global__ void k_scan1(int pbase) {
    __shared__ float s[1024];
    int plane = pbase + blockIdx.y;
    int gi = blockIdx.x * 1024 + threadIdx.x;
    int t = threadIdx.x;
    float x = g_ev[plane * EP + gi];
    s[t] = x;
    __syncthreads();
    for (int off = 1; off < 1024; off <<= 1) {
        float y = (t >= off) ? s[t - off] : 0.0f;
        __syncthreads();
        s[t] += y;
        __syncthreads();
    }
    g_ev[plane * EP + gi] = s[t];
    if (t == 1023) g_part[plane * 256 + blockIdx.x] = s[1023];
}

__global__ void k_scan2(int pbase) {
    __shared__ float s[256];
    int plane = pbase + blockIdx.y;
    int t = threadIdx.x;
    float x = g_part[plane * 256 + t];
    s[t] = x;
    __syncthreads();
    for (int off = 1; off < 256; off <<= 1) {
        float y = (t >= off) ? s[t - off] : 0.0f;
        __syncthreads();
        s[t] += y;
        __syncthreads();
    }
    g_part[plane * 256 + t] = s[t] - x;   // exclusive
}

__global__ void k_scan3(int pbase) {
    int plane = pbase + blockIdx.y;
    int gi = blockIdx.x * 1024 + threadIdx.x;
    g_ev[plane * EP + gi] += g_part[plane * 256 + blockIdx.x];
}

// ---------------- sigmoid via degree-9 Taylor, binomial moment combine ----------------
__device__ __forceinline__ float sig_combine(float x, const float* A) {
    float xp[10];
    xp[0] = 1.0f;
    #pragma unroll
    for (int p = 1; p < 10; p++) xp[p] = xp[p - 1] * x;
    float B0 = A[0];
    float B1 = xp[1] * A[0] - A[1];
    float B3 = xp[3] * A[0] - 3.0f * xp[2] * A[1] + 3.0f * xp[1] * A[2] - A[3];
    float B5 = xp[5] * A[0] - 5.0f * xp[4] * A[1] + 10.0f * xp[3] * A[2]
             - 10.0f * xp[2] * A[3] + 5.0f * xp[1] * A[4] - A[5];
    float B7 = xp[7] * A[0] - 7.0f * xp[6] * A[1] + 21.0f * xp[5] * A[2]
             - 35.0f * xp[4] * A[3] + 35.0f * xp[3] * A[4] - 21.0f * xp[2] * A[5]
             + 7.0f * xp[1] * A[6] - A[7];
    float B9 = xp[9] * A[0] - 9.0f * xp[8] * A[1] + 36.0f * xp[7] * A[2]
             - 84.0f * xp[6] * A[3] + 126.0f * xp[5] * A[4] - 126.0f * xp[4] * A[5]
             + 84.0f * xp[3] * A[6] - 36.0f * xp[2] * A[7] + 9.0f * xp[1] * A[8] - A[9];
    return 0.5f * B0 + 0.25f * B1 - 0.0208333333f * B3 + 0.0020833333f * B5
         - 2.1081349e-4f * B7 + 2.1357107e-5f * B9;
}

// ---------------- subtree moments -> sizes + inside ----------------
__global__ void k_subtree() {
    int k = blockIdx.x * blockDim.x + threadIdx.x;
    if (k >= MACC) return;
    int a = L_ + k;
    unsigned int pd = g_pos[a], pu = g_pos[NN + a];
    float T[10];
    #pragma unroll
    for (int i = 0; i < 10; i++) T[i] = g_ev[i * EP + pu] - g_ev[i * EP + pd];
    g_sizes[a] = T[0];
    g_ins[a] = sig_combine(g_alt[a], T);
}

// ---------------- final: out = outside + (leaf ? 0.5 : inside) ----------------
__global__ void k_final(float* __restrict__ out) {
    int n = blockIdx.x * blockDim.x + threadIdx.x;
    if (n >= NN) return;
    float x  = g_alt[n];
    float sz = g_sizes[n];
    unsigned int pd = g_pos[n];
    float A[10];
    float xp = 1.0f;
    #pragma unroll
    for (int i = 0; i < 10; i++) {
        A[i] = g_ev[(10 + i) * EP + pd] - sz * xp;   // strict ancestors only
        xp *= x;
    }
    float outside = sig_combine(x, A);
    out[n] = outside + (n < L_ ? 0.5f : g_ins[n]);
}

// ---------------- launch ----------------
extern "C" void kernel_launch(void* const* d_in, const int* in_sizes, int n_in,
                              void* d_out, int out_size) {
    const float* ew  = (const float*)d_in[0];
    const int*   src = (const int*)d_in[1];
    const int*   dst = (const int*)d_in[2];
    int M = in_sizes[0];   // 130560
    int nc = (M + CHUNK - 1) / CHUNK;   // 128

    k_init<<<NPAD / 256, 256>>>(M);

    // bucket sort (stable order via unique (wbits,idx) in-bucket sort)
    k_bhist<<<(M + 255) / 256, 256>>>(ew, M);
    k_bscan<<<1, 1024>>>();
    k_bscatter<<<(M + 255) / 256, 256>>>(ew, M);
    k_bsort<<<NB, 128>>>(src, dst);

    // tree build
    cudaFuncSetAttribute(k_phase1, cudaFuncAttributeMaxDynamicSharedMemorySize, L_ * 2);
    cudaFuncSetAttribute(k_phase2, cudaFuncAttributeMaxDynamicSharedMemorySize, L_ * 2);
    k_phase1<<<1, 1024, L_ * 2>>>(M, nc);
    k_phase2<<<nc, 1024, L_ * 2>>>(M);
    k_ascan<<<1, NCMAX>>>(nc);
    k_ascatter<<<(nc * CHUNK + 255) / 256, 256>>>(nc);

    // event sort + chain links
    k_bsort32_local_init<<<EVN / 2048, 1024>>>();
    for (int k = 4096; k <= EVN; k <<= 1) {
        for (int j = k >> 1; j >= 2048; j >>= 1)
            k_bsort32_global<<<(EVN / 2) / 256, 256>>>(j, k);
        k_bsort32_local_tail<<<EVN / 2048, 1024>>>(k);
    }
    k_vlink2<<<(2 * MACC + 255) / 256, 256>>>();

    // Euler tour + list ranking
    k_euler<<<(NN + 255) / 256, 256>>>();
    int s = 0;
    for (int r = 0; r < 18; r++) {
        k_rank<<<(ELEN + 1 + 255) / 256, 256>>>(s);
        s = 1 - s;
    }
    k_pos<<<(ELEN + 255) / 256, 256>>>(s);

    // subtree moments (planes 0..9)
    k_escatter<<<(L_ + 255) / 256, 256>>>();
    {
        dim3 g1(256, 10); k_scan1<<<g1, 1024>>>(0);
        dim3 g2(1, 10);   k_scan2<<<g2, 256>>>(0);
        dim3 g3(256, 10); k_scan3<<<g3, 1024>>>(0);
    }
    k_subtree<<<(MACC + 255) / 256, 256>>>();

    // ancestor path sums (planes 10..19) via Euler prefix
    k_pscatter<<<(NN + 255) / 256, 256>>>();
    {
        dim3 g1(256, 10); k_scan1<<<g1, 1024>>>(10);
        dim3 g2(1, 10);   k_scan2<<<g2, 256>>>(10);
        dim3 g3(256, 10); k_scan3<<<g3, 1024>>>(10);
    }

    k_final<<<(NN + 255) / 256, 256>>>((float*)d_out);
}